// round 7
// baseline (speedup 1.0000x reference)
#include <cuda_runtime.h>
#include <cuda_fp16.h>
#include <math.h>

#define D_MODEL 768
#define NHEAD 12
#define HD 64
#define BATCH 2
#define SEQ 2048
#define MROWS (BATCH*SEQ)   // 4096
#define NBH (BATCH*NHEAD)   // 24
#define NSPLIT 2

// -------- scratch (no allocations) --------
__device__ __half g_Q[NBH*SEQ*HD];
__device__ __half g_K[NBH*SEQ*HD];
__device__ __half g_V[NBH*SEQ*HD];
__device__ __half g_ctx[MROWS*D_MODEL];
__device__ __half g_xh[MROWS*D_MODEL];
__device__ __half g_Wqh[D_MODEL*D_MODEL];
__device__ __half g_Wkh[D_MODEL*D_MODEL];
__device__ __half g_Wvh[D_MODEL*D_MODEL];
__device__ __half g_Woh[D_MODEL*D_MODEL];
__device__ float  g_part[NSPLIT*NBH*SEQ*HD];   // normalized partial O
__device__ float  g_ml[NSPLIT*NBH*SEQ*2];      // per-row (m, l)

// -------- helpers --------
__device__ __forceinline__ unsigned smem_u32(const void* p) {
    return (unsigned)__cvta_generic_to_shared(p);
}
__device__ __forceinline__ unsigned pack2(float a, float b) {
    __half2 h = __floats2half2_rn(a, b);
    return *reinterpret_cast<unsigned*>(&h);
}
__device__ __forceinline__ float ex2f(float x) {
    float r; asm("ex2.approx.f32 %0, %1;" : "=f"(r) : "f"(x)); return r;
}
__device__ __forceinline__ void ldm4(unsigned& r0, unsigned& r1, unsigned& r2, unsigned& r3,
                                     unsigned addr) {
    asm volatile("ldmatrix.sync.aligned.m8n8.x4.shared.b16 {%0,%1,%2,%3},[%4];"
                 : "=r"(r0), "=r"(r1), "=r"(r2), "=r"(r3) : "r"(addr));
}
__device__ __forceinline__ void ldm4t(unsigned& r0, unsigned& r1, unsigned& r2, unsigned& r3,
                                      unsigned addr) {
    asm volatile("ldmatrix.sync.aligned.m8n8.x4.trans.shared.b16 {%0,%1,%2,%3},[%4];"
                 : "=r"(r0), "=r"(r1), "=r"(r2), "=r"(r3) : "r"(addr));
}
__device__ __forceinline__ void mma16816(float* c, const unsigned* a, unsigned b0, unsigned b1) {
    asm volatile(
        "mma.sync.aligned.m16n8k16.row.col.f32.f16.f16.f32 "
        "{%0,%1,%2,%3},{%4,%5,%6,%7},{%8,%9},{%0,%1,%2,%3};"
        : "+f"(c[0]), "+f"(c[1]), "+f"(c[2]), "+f"(c[3])
        : "r"(a[0]), "r"(a[1]), "r"(a[2]), "r"(a[3]), "r"(b0), "r"(b1));
}
__device__ __forceinline__ void cp16(unsigned dst, const void* src) {
    asm volatile("cp.async.cg.shared.global [%0], [%1], 16;" :: "r"(dst), "l"(src));
}
__device__ __forceinline__ void cp_commit() { asm volatile("cp.async.commit_group;"); }
__device__ __forceinline__ void cp_wait2() { asm volatile("cp.async.wait_group 2;"); }
__device__ __forceinline__ void cp_wait1() { asm volatile("cp.async.wait_group 1;"); }
__device__ __forceinline__ void cp_wait0() { asm volatile("cp.async.wait_group 0;"); }

// ============================================================
// fused fp32 -> fp16 conversion of x + all 4 weights
// ============================================================
#define N8X (MROWS*D_MODEL/8)
#define N8W (D_MODEL*D_MODEL/8)
#define N8TOT (N8X + 4*N8W)

__global__ __launch_bounds__(256) void cvt_all(
    const float* __restrict__ x,
    const float* __restrict__ wq, const float* __restrict__ wk,
    const float* __restrict__ wv, const float* __restrict__ wo,
    __half* __restrict__ xh,
    __half* __restrict__ wqh, __half* __restrict__ wkh,
    __half* __restrict__ wvh, __half* __restrict__ woh)
{
    int i = blockIdx.x * 256 + threadIdx.x;
    if (i >= N8TOT) return;
    const float* src;
    __half* dst;
    int off;
    if (i < N8X) { src = x; dst = xh; off = i; }
    else {
        int j = i - N8X;
        int seg = j / N8W;
        off = j - seg * N8W;
        src = (seg == 0) ? wq : (seg == 1) ? wk : (seg == 2) ? wv : wo;
        dst = (seg == 0) ? wqh : (seg == 1) ? wkh : (seg == 2) ? wvh : woh;
    }
    float4 a = *(const float4*)&src[(size_t)off * 8];
    float4 b = *(const float4*)&src[(size_t)off * 8 + 4];
    uint4 h;
    h.x = pack2(a.x, a.y); h.y = pack2(a.z, a.w);
    h.z = pack2(b.x, b.y); h.w = pack2(b.z, b.w);
    *(uint4*)&dst[(size_t)off * 8] = h;
}

// ============================================================
// fp16 GEMM core: 64m x 128n block, k-slab 32, 4-stage cp.async,
// 256 thr = 8 warps (2m x 4n), warp tile 32m x 32n.
// ============================================================
#define ALD 40
#define BLD 136
#define GSTAGES 4

template<bool OUT_HALF, bool SCATTER>
__device__ __forceinline__ void gemm_body(
    const __half* __restrict__ X, const __half* __restrict__ W,
    const float* __restrict__ bias, void* __restrict__ outp, float oscale,
    int row0, int col0)
{
    __shared__ __half As[GSTAGES][64 * ALD];
    __shared__ __half Bs[GSTAGES][32 * BLD];

    const int tid = threadIdx.x;
    const int lane = tid & 31;
    const int g = lane >> 2;
    const int t = lane & 3;
    const int wid = tid >> 5;
    const int wm = (wid & 1) * 32;
    const int wn = (wid >> 1) * 32;

    float acc[2][4][4];
#pragma unroll
    for (int i = 0; i < 2; i++)
#pragma unroll
        for (int j = 0; j < 4; j++)
#pragma unroll
            for (int k = 0; k < 4; k++) acc[i][j][k] = 0.f;

    auto submit = [&](int k0, int st) {
        {
            int ar = tid >> 2, ac = (tid & 3) * 8;
            cp16(smem_u32(&As[st][ar * ALD + ac]),
                 &X[(size_t)(row0 + ar) * 768 + k0 + ac]);
        }
#pragma unroll
        for (int i = 0; i < 2; i++) {
            int ci = tid + 256 * i;
            int br = ci >> 4, bc = (ci & 15) * 8;
            cp16(smem_u32(&Bs[st][br * BLD + bc]),
                 &W[(size_t)(k0 + br) * 768 + col0 + bc]);
        }
        cp_commit();
    };

    const int NK = 768 / 32;
    submit(0, 0);
    submit(32, 1);
    submit(64, 2);

    for (int k = 0; k < NK; k++) {
        const int s = k & (GSTAGES - 1);
        cp_wait2();
        __syncthreads();
        if (k + 3 < NK) submit((k + 3) * 32, (k + 3) & (GSTAGES - 1));

#pragma unroll
        for (int ks = 0; ks < 2; ks++) {
            unsigned a[2][4];
#pragma unroll
            for (int mt = 0; mt < 2; mt++)
                ldm4(a[mt][0], a[mt][1], a[mt][2], a[mt][3],
                     smem_u32(&As[s][(wm + mt * 16 + (lane & 15)) * ALD +
                                     ks * 16 + ((lane >> 4) << 3)]));
            unsigned b[2][4];
#pragma unroll
            for (int np = 0; np < 2; np++)
                ldm4t(b[np][0], b[np][1], b[np][2], b[np][3],
                      smem_u32(&Bs[s][(ks * 16 + (lane & 7) + ((lane >> 3) & 1) * 8) * BLD +
                                      wn + np * 16 + (lane >> 4) * 8]));
#pragma unroll
            for (int mt = 0; mt < 2; mt++)
#pragma unroll
                for (int np = 0; np < 2; np++) {
                    mma16816(acc[mt][np * 2], a[mt], b[np][0], b[np][1]);
                    mma16816(acc[mt][np * 2 + 1], a[mt], b[np][2], b[np][3]);
                }
        }
    }

#pragma unroll
    for (int nt = 0; nt < 4; nt++) {
        int col = col0 + wn + nt * 8 + 2 * t;
        float b0 = bias[col], b1 = bias[col + 1];
#pragma unroll
        for (int mt = 0; mt < 2; mt++)
#pragma unroll
            for (int hh = 0; hh < 2; hh++) {
                int m = row0 + wm + mt * 16 + g + hh * 8;
                float v0 = (acc[mt][nt][hh * 2] + b0) * oscale;
                float v1 = (acc[mt][nt][hh * 2 + 1] + b1) * oscale;
                if constexpr (OUT_HALF) {
                    __half* oh = (__half*)outp;
                    size_t idx;
                    if constexpr (SCATTER) {
                        int head = col >> 6, d = col & 63;
                        int bb = m >> 11, ss = m & 2047;
                        idx = ((size_t)(bb * NHEAD + head) * SEQ + ss) * HD + d;
                    } else {
                        idx = (size_t)m * 768 + col;
                    }
                    *(__half2*)&oh[idx] = __floats2half2_rn(v0, v1);
                } else {
                    float* of = (float*)outp;
                    float2 o; o.x = v0; o.y = v1;
                    *(float2*)&of[(size_t)m * 768 + col] = o;
                }
            }
    }
}

__global__ __launch_bounds__(256, 2) void gemm_qkv(
    const __half* __restrict__ X,
    const __half* __restrict__ Wq, const __half* __restrict__ Wk,
    const __half* __restrict__ Wv,
    const float* __restrict__ bq, const float* __restrict__ bk,
    const float* __restrict__ bv,
    __half* __restrict__ Qo, __half* __restrict__ Ko, __half* __restrict__ Vo,
    float qscale)
{
    const int z = blockIdx.z;
    const __half* W = (z == 0) ? Wq : (z == 1) ? Wk : Wv;
    const float* b  = (z == 0) ? bq : (z == 1) ? bk : bv;
    __half* o       = (z == 0) ? Qo : (z == 1) ? Ko : Vo;
    float sc        = (z == 0) ? qscale : 1.0f;
    gemm_body<true, true>(X, W, b, o, sc, blockIdx.y * 64, blockIdx.x * 128);
}

__global__ __launch_bounds__(256, 2) void gemm_out(
    const __half* __restrict__ X, const __half* __restrict__ W,
    const float* __restrict__ bias, float* __restrict__ out)
{
    gemm_body<false, false>(X, W, bias, out, 1.0f, blockIdx.y * 64, blockIdx.x * 128);
}

// ============================================================
// fp16 flash attention, split-KV: blockIdx.z selects key half.
// q-tile 128, 8 warps x 16 q-rows, 64-key tiles, 3-stage cp.async.
// Writes normalized partial O (fp32) + (m,l) per row.
// ============================================================
#define QLD 72
#define KVLD 72

__global__ __launch_bounds__(256, 2) void attn_f16(
    const __half* __restrict__ Qg, const __half* __restrict__ Kg,
    const __half* __restrict__ Vg, float* __restrict__ part,
    float* __restrict__ ml)
{
    extern __shared__ __half sm[];
    __half* Qs = sm;
    __half* KV = sm + 128 * QLD;

    const int tid = threadIdx.x;
    const int lane = tid & 31;
    const int g = lane >> 2;
    const int t = lane & 3;
    const int wid = tid >> 5;
    const int qr = wid * 16;
    const int bh = blockIdx.y;
    const int qt = blockIdx.x;
    const int split = blockIdx.z;

    const __half* Qp = Qg + ((size_t)bh * SEQ + qt * 128) * HD;
    const __half* Kbase = Kg + (size_t)bh * SEQ * HD;
    const __half* Vbase = Vg + (size_t)bh * SEQ * HD;

    const int NT = SEQ / 64 / NSPLIT;        // 16 tiles per split
    const int kt0 = split * NT;

    auto submit = [&](int kt, int st) {
        const __half* Kp = Kbase + (size_t)kt * 64 * HD;
        const __half* Vp = Vbase + (size_t)kt * 64 * HD;
        __half* Kd = KV + st * 2 * 64 * KVLD;
        __half* Vd = Kd + 64 * KVLD;
#pragma unroll
        for (int i = 0; i < 2; i++) {
            int ci = tid + 256 * i;
            int row = ci >> 3, c = ci & 7;
            cp16(smem_u32(&Kd[row * KVLD + c * 8]), &Kp[(size_t)row * HD + c * 8]);
            cp16(smem_u32(&Vd[row * KVLD + c * 8]), &Vp[(size_t)row * HD + c * 8]);
        }
        cp_commit();
    };

    submit(kt0, 0);
    submit(kt0 + 1, 1);
#pragma unroll
    for (int i = 0; i < 4; i++) {
        int ci = tid + 256 * i;
        int row = ci >> 3, c = ci & 7;
        *(uint4*)&Qs[row * QLD + c * 8] = *(const uint4*)&Qp[(size_t)row * HD + c * 8];
    }
    __syncthreads();
    unsigned qa[4][4];
#pragma unroll
    for (int ks = 0; ks < 4; ks++)
        ldm4(qa[ks][0], qa[ks][1], qa[ks][2], qa[ks][3],
             smem_u32(&Qs[(qr + (lane & 15)) * QLD + ks * 16 + ((lane >> 4) << 3)]));

    float acc[8][4];
    float rowm[2] = {-1e30f, -1e30f}, rowl[2] = {0.f, 0.f};
#pragma unroll
    for (int i = 0; i < 8; i++)
#pragma unroll
        for (int j = 0; j < 4; j++) acc[i][j] = 0.f;

    for (int kt = 0; kt < NT; kt++) {
        const int s = kt % 3;
        cp_wait1();
        __syncthreads();
        if (kt + 2 < NT) submit(kt0 + kt + 2, (kt + 2) % 3);

        const __half* Kd = KV + s * 2 * 64 * KVLD;
        const __half* Vd = Kd + 64 * KVLD;

        float sc[8][4];
#pragma unroll
        for (int i = 0; i < 8; i++)
#pragma unroll
            for (int j = 0; j < 4; j++) sc[i][j] = 0.f;

#pragma unroll
        for (int ks = 0; ks < 4; ks++) {
            unsigned kb[4][4];
#pragma unroll
            for (int kp = 0; kp < 4; kp++)
                ldm4(kb[kp][0], kb[kp][1], kb[kp][2], kb[kp][3],
                     smem_u32(&Kd[(kp * 16 + (lane & 15)) * KVLD +
                                  ks * 16 + ((lane >> 4) << 3)]));
#pragma unroll
            for (int kp = 0; kp < 4; kp++) {
                mma16816(sc[kp * 2],     qa[ks], kb[kp][0], kb[kp][2]);
                mma16816(sc[kp * 2 + 1], qa[ks], kb[kp][1], kb[kp][3]);
            }
        }

        float newm[2], corr[2];
#pragma unroll
        for (int hh = 0; hh < 2; hh++) {
            float mx = -1e30f;
#pragma unroll
            for (int nt = 0; nt < 8; nt++)
                mx = fmaxf(mx, fmaxf(sc[nt][hh * 2], sc[nt][hh * 2 + 1]));
            mx = fmaxf(mx, __shfl_xor_sync(0xffffffffu, mx, 1));
            mx = fmaxf(mx, __shfl_xor_sync(0xffffffffu, mx, 2));
            newm[hh] = fmaxf(rowm[hh], mx);
            corr[hh] = ex2f(rowm[hh] - newm[hh]);
            rowm[hh] = newm[hh];
#pragma unroll
            for (int nt = 0; nt < 8; nt++) {
                acc[nt][hh * 2] *= corr[hh];
                acc[nt][hh * 2 + 1] *= corr[hh];
            }
        }

        unsigned ph[4][4];
        float ps0 = 0.f, ps1 = 0.f;
#pragma unroll
        for (int nt = 0; nt < 8; nt++) {
            __half2 e0 = h2exp2(__floats2half2_rn(sc[nt][0] - newm[0], sc[nt][1] - newm[0]));
            __half2 e1 = h2exp2(__floats2half2_rn(sc[nt][2] - newm[1], sc[nt][3] - newm[1]));
            ph[nt >> 1][(nt & 1) * 2]     = *reinterpret_cast<unsigned*>(&e0);
            ph[nt >> 1][(nt & 1) * 2 + 1] = *reinterpret_cast<unsigned*>(&e1);
            float2 f0 = __half22float2(e0);
            float2 f1 = __half22float2(e1);
            ps0 += f0.x + f0.y;
            ps1 += f1.x + f1.y;
        }
        ps0 += __shfl_xor_sync(0xffffffffu, ps0, 1);
        ps0 += __shfl_xor_sync(0xffffffffu, ps0, 2);
        ps1 += __shfl_xor_sync(0xffffffffu, ps1, 1);
        ps1 += __shfl_xor_sync(0xffffffffu, ps1, 2);
        rowl[0] = rowl[0] * corr[0] + ps0;
        rowl[1] = rowl[1] * corr[1] + ps1;

#pragma unroll
        for (int ks = 0; ks < 4; ks++) {
            unsigned vb[4][4];
#pragma unroll
            for (int dp = 0; dp < 4; dp++)
                ldm4t(vb[dp][0], vb[dp][1], vb[dp][2], vb[dp][3],
                      smem_u32(&Vd[(ks * 16 + (lane & 7) + ((lane >> 3) & 1) * 8) * KVLD +
                                   dp * 16 + (lane >> 4) * 8]));
#pragma unroll
            for (int dp = 0; dp < 4; dp++) {
                mma16816(acc[dp * 2],     ph[ks], vb[dp][0], vb[dp][1]);
                mma16816(acc[dp * 2 + 1], ph[ks], vb[dp][2], vb[dp][3]);
            }
        }
    }

    // ---- epilogue: normalized partial + (m,l) ----
    const size_t pbase = ((size_t)split * NBH + bh) * SEQ;
#pragma unroll
    for (int hh = 0; hh < 2; hh++) {
        int q = qt * 128 + qr + g + hh * 8;
        float inv = 1.f / rowl[hh];
#pragma unroll
        for (int nt = 0; nt < 8; nt++) {
            int d = nt * 8 + 2 * t;
            float2 o;
            o.x = acc[nt][hh * 2] * inv;
            o.y = acc[nt][hh * 2 + 1] * inv;
            *(float2*)&part[(pbase + q) * HD + d] = o;
        }
        if (t == 0)
            *(float2*)&ml[(pbase + q) * 2] = make_float2(rowm[hh], rowl[hh]);
    }
}

// ============================================================
// combine the NSPLIT partials -> fp16 ctx in [B,S,D] layout
// ============================================================
#define NCOMB (NBH*SEQ*HD/4)   // threads, 4 floats each

__global__ __launch_bounds__(256) void attn_combine(
    const float* __restrict__ part, const float* __restrict__ ml,
    __half* __restrict__ ctx)
{
    int i = blockIdx.x * 256 + threadIdx.x;
    if (i >= NCOMB) return;
    int row = i >> 4;               // bh*SEQ + q
    int d = (i & 15) * 4;
    float2 ml0 = *(const float2*)&ml[(size_t)row * 2];
    float2 ml1 = *(const float2*)&ml[((size_t)NBH * SEQ + row) * 2];
    float mstar = fmaxf(ml0.x, ml1.x);
    float w0 = ml0.y * ex2f(ml0.x - mstar);
    float w1 = ml1.y * ex2f(ml1.x - mstar);
    float inv = 1.f / (w0 + w1);
    w0 *= inv; w1 *= inv;
    float4 o0 = *(const float4*)&part[(size_t)row * HD + d];
    float4 o1 = *(const float4*)&part[((size_t)NBH * SEQ + row) * HD + d];
    int bh = row >> 11, q = row & 2047;
    int bb = bh / NHEAD, head = bh % NHEAD;
    uint2 h;
    h.x = pack2(w0 * o0.x + w1 * o1.x, w0 * o0.y + w1 * o1.y);
    h.y = pack2(w0 * o0.z + w1 * o1.z, w0 * o0.w + w1 * o1.w);
    *(uint2*)&ctx[((size_t)(bb * SEQ + q)) * D_MODEL + head * HD + d] = h;
}

// ============================================================
extern "C" void kernel_launch(void* const* d_in, const int* in_sizes, int n_in,
                              void* d_out, int out_size)
{
    const float* x  = (const float*)d_in[0];
    const float* Wq = (const float*)d_in[1];
    const float* bq = (const float*)d_in[2];
    const float* Wk = (const float*)d_in[3];
    const float* bk = (const float*)d_in[4];
    const float* Wv = (const float*)d_in[5];
    const float* bv = (const float*)d_in[6];
    const float* Wo = (const float*)d_in[7];
    const float* bo = (const float*)d_in[8];
    float* out = (float*)d_out;

    __half *Qp, *Kp, *Vp, *ctxp, *xh, *Wqh, *Wkh, *Wvh, *Woh;
    float *partp, *mlp;
    cudaGetSymbolAddress((void**)&Qp, g_Q);
    cudaGetSymbolAddress((void**)&Kp, g_K);
    cudaGetSymbolAddress((void**)&Vp, g_V);
    cudaGetSymbolAddress((void**)&ctxp, g_ctx);
    cudaGetSymbolAddress((void**)&xh, g_xh);
    cudaGetSymbolAddress((void**)&Wqh, g_Wqh);
    cudaGetSymbolAddress((void**)&Wkh, g_Wkh);
    cudaGetSymbolAddress((void**)&Wvh, g_Wvh);
    cudaGetSymbolAddress((void**)&Woh, g_Woh);
    cudaGetSymbolAddress((void**)&partp, g_part);
    cudaGetSymbolAddress((void**)&mlp, g_ml);

    const size_t attn_smem = (size_t)(128 * QLD + 6 * 64 * KVLD) * sizeof(__half);
    cudaFuncSetAttribute(attn_f16, cudaFuncAttributeMaxDynamicSharedMemorySize,
                         (int)attn_smem);

    cvt_all<<<(N8TOT + 255) / 256, 256>>>(x, Wq, Wk, Wv, Wo,
                                          xh, Wqh, Wkh, Wvh, Woh);

    const float QSCALE = 0.125f * 1.4426950408889634f;
    dim3 gq(768 / 128, MROWS / 64, 3);    // (6, 64, 3)
    gemm_qkv<<<gq, 256>>>(xh, Wqh, Wkh, Wvh, bq, bk, bv, Qp, Kp, Vp, QSCALE);

    dim3 ga(SEQ / 128, NBH, NSPLIT);      // (16, 24, 2)
    attn_f16<<<ga, 256, attn_smem>>>(Qp, Kp, Vp, partp, mlp);

    attn_combine<<<(NCOMB + 255) / 256, 256>>>(partp, mlp, ctxp);

    dim3 gg(768 / 128, MROWS / 64);       // (6, 64)
    gemm_out<<<gg, 256>>>(ctxp, Woh, bo, out);
}

// round 8
// speedup vs baseline: 1.0575x; 1.0575x over previous
#include <cuda_runtime.h>
#include <cuda_fp16.h>
#include <math.h>

#define D_MODEL 768
#define NHEAD 12
#define HD 64
#define BATCH 2
#define SEQ 2048
#define MROWS (BATCH*SEQ)   // 4096
#define NBH (BATCH*NHEAD)   // 24

// -------- scratch (fp16; no allocations) --------
__device__ __half g_Q[NBH*SEQ*HD];
__device__ __half g_K[NBH*SEQ*HD];
__device__ __half g_V[NBH*SEQ*HD];
__device__ __half g_ctx[MROWS*D_MODEL];
__device__ __half g_xh[MROWS*D_MODEL];
__device__ __half g_Wqh[D_MODEL*D_MODEL];
__device__ __half g_Wkh[D_MODEL*D_MODEL];
__device__ __half g_Wvh[D_MODEL*D_MODEL];
__device__ __half g_Woh[D_MODEL*D_MODEL];

// -------- helpers --------
__device__ __forceinline__ unsigned smem_u32(const void* p) {
    return (unsigned)__cvta_generic_to_shared(p);
}
__device__ __forceinline__ unsigned pack2(float a, float b) {
    __half2 h = __floats2half2_rn(a, b);
    return *reinterpret_cast<unsigned*>(&h);
}
__device__ __forceinline__ float ex2f(float x) {
    float r; asm("ex2.approx.f32 %0, %1;" : "=f"(r) : "f"(x)); return r;
}
__device__ __forceinline__ void ldm4(unsigned& r0, unsigned& r1, unsigned& r2, unsigned& r3,
                                     unsigned addr) {
    asm volatile("ldmatrix.sync.aligned.m8n8.x4.shared.b16 {%0,%1,%2,%3},[%4];"
                 : "=r"(r0), "=r"(r1), "=r"(r2), "=r"(r3) : "r"(addr));
}
__device__ __forceinline__ void ldm4t(unsigned& r0, unsigned& r1, unsigned& r2, unsigned& r3,
                                      unsigned addr) {
    asm volatile("ldmatrix.sync.aligned.m8n8.x4.trans.shared.b16 {%0,%1,%2,%3},[%4];"
                 : "=r"(r0), "=r"(r1), "=r"(r2), "=r"(r3) : "r"(addr));
}
__device__ __forceinline__ void mma16816(float* c, const unsigned* a, unsigned b0, unsigned b1) {
    asm volatile(
        "mma.sync.aligned.m16n8k16.row.col.f32.f16.f16.f32 "
        "{%0,%1,%2,%3},{%4,%5,%6,%7},{%8,%9},{%0,%1,%2,%3};"
        : "+f"(c[0]), "+f"(c[1]), "+f"(c[2]), "+f"(c[3])
        : "r"(a[0]), "r"(a[1]), "r"(a[2]), "r"(a[3]), "r"(b0), "r"(b1));
}
__device__ __forceinline__ void cp16(unsigned dst, const void* src) {
    asm volatile("cp.async.cg.shared.global [%0], [%1], 16;" :: "r"(dst), "l"(src));
}
__device__ __forceinline__ void cp_commit() { asm volatile("cp.async.commit_group;"); }
__device__ __forceinline__ void cp_wait2() { asm volatile("cp.async.wait_group 2;"); }
__device__ __forceinline__ void cp_wait1() { asm volatile("cp.async.wait_group 1;"); }
__device__ __forceinline__ void cp_wait0() { asm volatile("cp.async.wait_group 0;"); }

// ============================================================
// fused fp32 -> fp16 conversion of x + all 4 weights
// ============================================================
#define N8X (MROWS*D_MODEL/8)
#define N8W (D_MODEL*D_MODEL/8)
#define N8TOT (N8X + 4*N8W)

__global__ __launch_bounds__(256) void cvt_all(
    const float* __restrict__ x,
    const float* __restrict__ wq, const float* __restrict__ wk,
    const float* __restrict__ wv, const float* __restrict__ wo,
    __half* __restrict__ xh,
    __half* __restrict__ wqh, __half* __restrict__ wkh,
    __half* __restrict__ wvh, __half* __restrict__ woh)
{
    int i = blockIdx.x * 256 + threadIdx.x;
    if (i >= N8TOT) return;
    const float* src;
    __half* dst;
    int off;
    if (i < N8X) { src = x; dst = xh; off = i; }
    else {
        int j = i - N8X;
        int seg = j / N8W;
        off = j - seg * N8W;
        src = (seg == 0) ? wq : (seg == 1) ? wk : (seg == 2) ? wv : wo;
        dst = (seg == 0) ? wqh : (seg == 1) ? wkh : (seg == 2) ? wvh : woh;
    }
    float4 a = *(const float4*)&src[(size_t)off * 8];
    float4 b = *(const float4*)&src[(size_t)off * 8 + 4];
    uint4 h;
    h.x = pack2(a.x, a.y); h.y = pack2(a.z, a.w);
    h.z = pack2(b.x, b.y); h.w = pack2(b.z, b.w);
    *(uint4*)&dst[(size_t)off * 8] = h;
}

// ============================================================
// fp16 GEMM core: 64m x 128n block, k-slab 32, 4-stage cp.async,
// 256 thr = 8 warps (2m x 4n), warp tile 32m x 32n.
// ============================================================
#define ALD 40
#define BLD 136
#define GSTAGES 4

template<bool OUT_HALF, bool SCATTER>
__device__ __forceinline__ void gemm_body(
    const __half* __restrict__ X, const __half* __restrict__ W,
    const float* __restrict__ bias, void* __restrict__ outp, float oscale,
    int row0, int col0)
{
    __shared__ __half As[GSTAGES][64 * ALD];
    __shared__ __half Bs[GSTAGES][32 * BLD];

    const int tid = threadIdx.x;
    const int lane = tid & 31;
    const int g = lane >> 2;
    const int t = lane & 3;
    const int wid = tid >> 5;
    const int wm = (wid & 1) * 32;
    const int wn = (wid >> 1) * 32;

    float acc[2][4][4];
#pragma unroll
    for (int i = 0; i < 2; i++)
#pragma unroll
        for (int j = 0; j < 4; j++)
#pragma unroll
            for (int k = 0; k < 4; k++) acc[i][j][k] = 0.f;

    auto submit = [&](int k0, int st) {
        {
            int ar = tid >> 2, ac = (tid & 3) * 8;
            cp16(smem_u32(&As[st][ar * ALD + ac]),
                 &X[(size_t)(row0 + ar) * 768 + k0 + ac]);
        }
#pragma unroll
        for (int i = 0; i < 2; i++) {
            int ci = tid + 256 * i;
            int br = ci >> 4, bc = (ci & 15) * 8;
            cp16(smem_u32(&Bs[st][br * BLD + bc]),
                 &W[(size_t)(k0 + br) * 768 + col0 + bc]);
        }
        cp_commit();
    };

    const int NK = 768 / 32;
    submit(0, 0);
    submit(32, 1);
    submit(64, 2);

    for (int k = 0; k < NK; k++) {
        const int s = k & (GSTAGES - 1);
        cp_wait2();
        __syncthreads();
        if (k + 3 < NK) submit((k + 3) * 32, (k + 3) & (GSTAGES - 1));

#pragma unroll
        for (int ks = 0; ks < 2; ks++) {
            unsigned a[2][4];
#pragma unroll
            for (int mt = 0; mt < 2; mt++)
                ldm4(a[mt][0], a[mt][1], a[mt][2], a[mt][3],
                     smem_u32(&As[s][(wm + mt * 16 + (lane & 15)) * ALD +
                                     ks * 16 + ((lane >> 4) << 3)]));
            unsigned b[2][4];
#pragma unroll
            for (int np = 0; np < 2; np++)
                ldm4t(b[np][0], b[np][1], b[np][2], b[np][3],
                      smem_u32(&Bs[s][(ks * 16 + (lane & 7) + ((lane >> 3) & 1) * 8) * BLD +
                                      wn + np * 16 + (lane >> 4) * 8]));
#pragma unroll
            for (int mt = 0; mt < 2; mt++)
#pragma unroll
                for (int np = 0; np < 2; np++) {
                    mma16816(acc[mt][np * 2], a[mt], b[np][0], b[np][1]);
                    mma16816(acc[mt][np * 2 + 1], a[mt], b[np][2], b[np][3]);
                }
        }
    }

#pragma unroll
    for (int nt = 0; nt < 4; nt++) {
        int col = col0 + wn + nt * 8 + 2 * t;
        float b0 = bias[col], b1 = bias[col + 1];
#pragma unroll
        for (int mt = 0; mt < 2; mt++)
#pragma unroll
            for (int hh = 0; hh < 2; hh++) {
                int m = row0 + wm + mt * 16 + g + hh * 8;
                float v0 = (acc[mt][nt][hh * 2] + b0) * oscale;
                float v1 = (acc[mt][nt][hh * 2 + 1] + b1) * oscale;
                if constexpr (OUT_HALF) {
                    __half* oh = (__half*)outp;
                    size_t idx;
                    if constexpr (SCATTER) {
                        int head = col >> 6, d = col & 63;
                        int bb = m >> 11, ss = m & 2047;
                        idx = ((size_t)(bb * NHEAD + head) * SEQ + ss) * HD + d;
                    } else {
                        idx = (size_t)m * 768 + col;
                    }
                    *(__half2*)&oh[idx] = __floats2half2_rn(v0, v1);
                } else {
                    float* of = (float*)outp;
                    float2 o; o.x = v0; o.y = v1;
                    *(float2*)&of[(size_t)m * 768 + col] = o;
                }
            }
    }
}

__global__ __launch_bounds__(256, 2) void gemm_qkv(
    const __half* __restrict__ X,
    const __half* __restrict__ Wq, const __half* __restrict__ Wk,
    const __half* __restrict__ Wv,
    const float* __restrict__ bq, const float* __restrict__ bk,
    const float* __restrict__ bv,
    __half* __restrict__ Qo, __half* __restrict__ Ko, __half* __restrict__ Vo,
    float qscale)
{
    const int z = blockIdx.z;
    const __half* W = (z == 0) ? Wq : (z == 1) ? Wk : Wv;
    const float* b  = (z == 0) ? bq : (z == 1) ? bk : bv;
    __half* o       = (z == 0) ? Qo : (z == 1) ? Ko : Vo;
    float sc        = (z == 0) ? qscale : 1.0f;
    gemm_body<true, true>(X, W, b, o, sc, blockIdx.y * 64, blockIdx.x * 128);
}

__global__ __launch_bounds__(256, 2) void gemm_out(
    const __half* __restrict__ X, const __half* __restrict__ W,
    const float* __restrict__ bias, float* __restrict__ out)
{
    gemm_body<false, false>(X, W, bias, out, 1.0f, blockIdx.y * 64, blockIdx.x * 128);
}

// ============================================================
// fp16 flash attention (R5 version): q-tile 128, 8 warps x 16 q,
// 64-key tiles, 3-stage cp.async, base-2 softmax w/ h2exp2.
// Scale (1/8)*log2(e) folded into the Q projection.
// ============================================================
#define QLD 72
#define KVLD 72

__global__ __launch_bounds__(256, 2) void attn_f16(
    const __half* __restrict__ Qg, const __half* __restrict__ Kg,
    const __half* __restrict__ Vg, __half* __restrict__ ctx)
{
    extern __shared__ __half sm[];
    __half* Qs = sm;
    __half* KV = sm + 128 * QLD;

    const int tid = threadIdx.x;
    const int lane = tid & 31;
    const int g = lane >> 2;
    const int t = lane & 3;
    const int wid = tid >> 5;
    const int qr = wid * 16;
    const int bh = blockIdx.y;
    const int qt = blockIdx.x;

    const __half* Qp = Qg + ((size_t)bh * SEQ + qt * 128) * HD;
    const __half* Kbase = Kg + (size_t)bh * SEQ * HD;
    const __half* Vbase = Vg + (size_t)bh * SEQ * HD;

    const int NT = SEQ / 64;

    auto submit = [&](int kt, int st) {
        const __half* Kp = Kbase + (size_t)kt * 64 * HD;
        const __half* Vp = Vbase + (size_t)kt * 64 * HD;
        __half* Kd = KV + st * 2 * 64 * KVLD;
        __half* Vd = Kd + 64 * KVLD;
#pragma unroll
        for (int i = 0; i < 2; i++) {
            int ci = tid + 256 * i;
            int row = ci >> 3, c = ci & 7;
            cp16(smem_u32(&Kd[row * KVLD + c * 8]), &Kp[(size_t)row * HD + c * 8]);
            cp16(smem_u32(&Vd[row * KVLD + c * 8]), &Vp[(size_t)row * HD + c * 8]);
        }
        cp_commit();
    };

    submit(0, 0);
    submit(1, 1);
#pragma unroll
    for (int i = 0; i < 4; i++) {
        int ci = tid + 256 * i;
        int row = ci >> 3, c = ci & 7;
        *(uint4*)&Qs[row * QLD + c * 8] = *(const uint4*)&Qp[(size_t)row * HD + c * 8];
    }
    __syncthreads();
    unsigned qa[4][4];
#pragma unroll
    for (int ks = 0; ks < 4; ks++)
        ldm4(qa[ks][0], qa[ks][1], qa[ks][2], qa[ks][3],
             smem_u32(&Qs[(qr + (lane & 15)) * QLD + ks * 16 + ((lane >> 4) << 3)]));

    float acc[8][4];
    float rowm[2] = {-1e30f, -1e30f}, rowl[2] = {0.f, 0.f};
#pragma unroll
    for (int i = 0; i < 8; i++)
#pragma unroll
        for (int j = 0; j < 4; j++) acc[i][j] = 0.f;

    for (int kt = 0; kt < NT; kt++) {
        const int s = kt % 3;
        cp_wait1();
        __syncthreads();
        if (kt + 2 < NT) submit(kt + 2, (kt + 2) % 3);

        const __half* Kd = KV + s * 2 * 64 * KVLD;
        const __half* Vd = Kd + 64 * KVLD;

        float sc[8][4];
#pragma unroll
        for (int i = 0; i < 8; i++)
#pragma unroll
            for (int j = 0; j < 4; j++) sc[i][j] = 0.f;

#pragma unroll
        for (int ks = 0; ks < 4; ks++) {
            unsigned kb[4][4];
#pragma unroll
            for (int kp = 0; kp < 4; kp++)
                ldm4(kb[kp][0], kb[kp][1], kb[kp][2], kb[kp][3],
                     smem_u32(&Kd[(kp * 16 + (lane & 15)) * KVLD +
                                  ks * 16 + ((lane >> 4) << 3)]));
#pragma unroll
            for (int kp = 0; kp < 4; kp++) {
                mma16816(sc[kp * 2],     qa[ks], kb[kp][0], kb[kp][2]);
                mma16816(sc[kp * 2 + 1], qa[ks], kb[kp][1], kb[kp][3]);
            }
        }

        float newm[2], corr[2];
#pragma unroll
        for (int hh = 0; hh < 2; hh++) {
            float mx = -1e30f;
#pragma unroll
            for (int nt = 0; nt < 8; nt++)
                mx = fmaxf(mx, fmaxf(sc[nt][hh * 2], sc[nt][hh * 2 + 1]));
            mx = fmaxf(mx, __shfl_xor_sync(0xffffffffu, mx, 1));
            mx = fmaxf(mx, __shfl_xor_sync(0xffffffffu, mx, 2));
            newm[hh] = fmaxf(rowm[hh], mx);
            corr[hh] = ex2f(rowm[hh] - newm[hh]);
            rowm[hh] = newm[hh];
#pragma unroll
            for (int nt = 0; nt < 8; nt++) {
                acc[nt][hh * 2] *= corr[hh];
                acc[nt][hh * 2 + 1] *= corr[hh];
            }
        }

        unsigned ph[4][4];
        float ps0 = 0.f, ps1 = 0.f;
#pragma unroll
        for (int nt = 0; nt < 8; nt++) {
            __half2 e0 = h2exp2(__floats2half2_rn(sc[nt][0] - newm[0], sc[nt][1] - newm[0]));
            __half2 e1 = h2exp2(__floats2half2_rn(sc[nt][2] - newm[1], sc[nt][3] - newm[1]));
            ph[nt >> 1][(nt & 1) * 2]     = *reinterpret_cast<unsigned*>(&e0);
            ph[nt >> 1][(nt & 1) * 2 + 1] = *reinterpret_cast<unsigned*>(&e1);
            float2 f0 = __half22float2(e0);
            float2 f1 = __half22float2(e1);
            ps0 += f0.x + f0.y;
            ps1 += f1.x + f1.y;
        }
        ps0 += __shfl_xor_sync(0xffffffffu, ps0, 1);
        ps0 += __shfl_xor_sync(0xffffffffu, ps0, 2);
        ps1 += __shfl_xor_sync(0xffffffffu, ps1, 1);
        ps1 += __shfl_xor_sync(0xffffffffu, ps1, 2);
        rowl[0] = rowl[0] * corr[0] + ps0;
        rowl[1] = rowl[1] * corr[1] + ps1;

#pragma unroll
        for (int ks = 0; ks < 4; ks++) {
            unsigned vb[4][4];
#pragma unroll
            for (int dp = 0; dp < 4; dp++)
                ldm4t(vb[dp][0], vb[dp][1], vb[dp][2], vb[dp][3],
                      smem_u32(&Vd[(ks * 16 + (lane & 7) + ((lane >> 3) & 1) * 8) * KVLD +
                                   dp * 16 + (lane >> 4) * 8]));
#pragma unroll
            for (int dp = 0; dp < 4; dp++) {
                mma16816(acc[dp * 2],     ph[ks], vb[dp][0], vb[dp][1]);
                mma16816(acc[dp * 2 + 1], ph[ks], vb[dp][2], vb[dp][3]);
            }
        }
    }

    const int bb = bh / NHEAD;
    const int head = bh % NHEAD;
#pragma unroll
    for (int hh = 0; hh < 2; hh++) {
        int q = qt * 128 + qr + g + hh * 8;
        float inv = 1.f / rowl[hh];
#pragma unroll
        for (int nt = 0; nt < 8; nt++) {
            int d = nt * 8 + 2 * t;
            *(__half2*)&ctx[(size_t)(bb * SEQ + q) * D_MODEL + head * HD + d] =
                __floats2half2_rn(acc[nt][hh * 2] * inv, acc[nt][hh * 2 + 1] * inv);
        }
    }
}

// ============================================================
extern "C" void kernel_launch(void* const* d_in, const int* in_sizes, int n_in,
                              void* d_out, int out_size)
{
    const float* x  = (const float*)d_in[0];
    const float* Wq = (const float*)d_in[1];
    const float* bq = (const float*)d_in[2];
    const float* Wk = (const float*)d_in[3];
    const float* bk = (const float*)d_in[4];
    const float* Wv = (const float*)d_in[5];
    const float* bv = (const float*)d_in[6];
    const float* Wo = (const float*)d_in[7];
    const float* bo = (const float*)d_in[8];
    float* out = (float*)d_out;

    __half *Qp, *Kp, *Vp, *ctxp, *xh, *Wqh, *Wkh, *Wvh, *Woh;
    cudaGetSymbolAddress((void**)&Qp, g_Q);
    cudaGetSymbolAddress((void**)&Kp, g_K);
    cudaGetSymbolAddress((void**)&Vp, g_V);
    cudaGetSymbolAddress((void**)&ctxp, g_ctx);
    cudaGetSymbolAddress((void**)&xh, g_xh);
    cudaGetSymbolAddress((void**)&Wqh, g_Wqh);
    cudaGetSymbolAddress((void**)&Wkh, g_Wkh);
    cudaGetSymbolAddress((void**)&Wvh, g_Wvh);
    cudaGetSymbolAddress((void**)&Woh, g_Woh);

    const size_t attn_smem = (size_t)(128 * QLD + 6 * 64 * KVLD) * sizeof(__half);
    cudaFuncSetAttribute(attn_f16, cudaFuncAttributeMaxDynamicSharedMemorySize,
                         (int)attn_smem);

    cvt_all<<<(N8TOT + 255) / 256, 256>>>(x, Wq, Wk, Wv, Wo,
                                          xh, Wqh, Wkh, Wvh, Woh);

    const float QSCALE = 0.125f * 1.4426950408889634f;
    dim3 gq(768 / 128, MROWS / 64, 3);    // (6, 64, 3)
    gemm_qkv<<<gq, 256>>>(xh, Wqh, Wkh, Wvh, bq, bk, bv, Qp, Kp, Vp, QSCALE);

    dim3 ga(SEQ / 128, NBH);              // (16, 24)
    attn_f16<<<ga, 256, attn_smem>>>(Qp, Kp, Vp, ctxp);

    dim3 gg(768 / 128, MROWS / 64);       // (6, 64)
    gemm_out<<<gg, 256>>>(ctxp, Woh, bo, out);
}

// round 9
// speedup vs baseline: 1.1042x; 1.0442x over previous
#include <cuda_runtime.h>
#include <cuda_fp16.h>
#include <math.h>

#define D_MODEL 768
#define NHEAD 12
#define HD 64
#define BATCH 2
#define SEQ 2048
#define MROWS (BATCH*SEQ)   // 4096
#define NBH (BATCH*NHEAD)   // 24

// -------- scratch (fp16; no allocations) --------
__device__ __half g_Q[NBH*SEQ*HD];
__device__ __half g_K[NBH*SEQ*HD];
__device__ __half g_V[NBH*SEQ*HD];
__device__ __half g_ctx[MROWS*D_MODEL];
__device__ __half g_xh[MROWS*D_MODEL];
__device__ __half g_Wqh[D_MODEL*D_MODEL];
__device__ __half g_Wkh[D_MODEL*D_MODEL];
__device__ __half g_Wvh[D_MODEL*D_MODEL];
__device__ __half g_Woh[D_MODEL*D_MODEL];

// -------- helpers --------
__device__ __forceinline__ unsigned smem_u32(const void* p) {
    return (unsigned)__cvta_generic_to_shared(p);
}
__device__ __forceinline__ unsigned pack2(float a, float b) {
    __half2 h = __floats2half2_rn(a, b);
    return *reinterpret_cast<unsigned*>(&h);
}
__device__ __forceinline__ float ex2f(float x) {
    float r; asm("ex2.approx.f32 %0, %1;" : "=f"(r) : "f"(x)); return r;
}
__device__ __forceinline__ void ldm4(unsigned& r0, unsigned& r1, unsigned& r2, unsigned& r3,
                                     unsigned addr) {
    asm volatile("ldmatrix.sync.aligned.m8n8.x4.shared.b16 {%0,%1,%2,%3},[%4];"
                 : "=r"(r0), "=r"(r1), "=r"(r2), "=r"(r3) : "r"(addr));
}
__device__ __forceinline__ void ldm4t(unsigned& r0, unsigned& r1, unsigned& r2, unsigned& r3,
                                      unsigned addr) {
    asm volatile("ldmatrix.sync.aligned.m8n8.x4.trans.shared.b16 {%0,%1,%2,%3},[%4];"
                 : "=r"(r0), "=r"(r1), "=r"(r2), "=r"(r3) : "r"(addr));
}
__device__ __forceinline__ void mma16816(float* c, const unsigned* a, unsigned b0, unsigned b1) {
    asm volatile(
        "mma.sync.aligned.m16n8k16.row.col.f32.f16.f16.f32 "
        "{%0,%1,%2,%3},{%4,%5,%6,%7},{%8,%9},{%0,%1,%2,%3};"
        : "+f"(c[0]), "+f"(c[1]), "+f"(c[2]), "+f"(c[3])
        : "r"(a[0]), "r"(a[1]), "r"(a[2]), "r"(a[3]), "r"(b0), "r"(b1));
}
__device__ __forceinline__ void cp16(unsigned dst, const void* src) {
    asm volatile("cp.async.cg.shared.global [%0], [%1], 16;" :: "r"(dst), "l"(src));
}
__device__ __forceinline__ void cp_commit() { asm volatile("cp.async.commit_group;"); }
__device__ __forceinline__ void cp_wait2() { asm volatile("cp.async.wait_group 2;"); }
__device__ __forceinline__ void cp_wait1() { asm volatile("cp.async.wait_group 1;"); }

// ============================================================
// fused fp32 -> fp16 conversion of x + all 4 weights
// ============================================================
#define N8X (MROWS*D_MODEL/8)
#define N8W (D_MODEL*D_MODEL/8)
#define N8TOT (N8X + 4*N8W)

__global__ __launch_bounds__(256) void cvt_all(
    const float* __restrict__ x,
    const float* __restrict__ wq, const float* __restrict__ wk,
    const float* __restrict__ wv, const float* __restrict__ wo,
    __half* __restrict__ xh,
    __half* __restrict__ wqh, __half* __restrict__ wkh,
    __half* __restrict__ wvh, __half* __restrict__ woh)
{
    int i = blockIdx.x * 256 + threadIdx.x;
    if (i >= N8TOT) return;
    const float* src;
    __half* dst;
    int off;
    if (i < N8X) { src = x; dst = xh; off = i; }
    else {
        int j = i - N8X;
        int seg = j / N8W;
        off = j - seg * N8W;
        src = (seg == 0) ? wq : (seg == 1) ? wk : (seg == 2) ? wv : wo;
        dst = (seg == 0) ? wqh : (seg == 1) ? wkh : (seg == 2) ? wvh : woh;
    }
    float4 a = *(const float4*)&src[(size_t)off * 8];
    float4 b = *(const float4*)&src[(size_t)off * 8 + 4];
    uint4 h;
    h.x = pack2(a.x, a.y); h.y = pack2(a.z, a.w);
    h.z = pack2(b.x, b.y); h.w = pack2(b.z, b.w);
    *(uint4*)&dst[(size_t)off * 8] = h;
}

// ============================================================
// fp16 GEMM core (R6 config): 128m x 128n block, k-slab 32,
// 4-stage cp.async, 256 thr = 8 warps (4m x 2n), warp 32m x 64n.
// ============================================================
#define ALD 40
#define BLD 136
#define GSTAGES 4

template<bool OUT_HALF, bool SCATTER>
__device__ __forceinline__ void gemm_body(
    const __half* __restrict__ X, const __half* __restrict__ W,
    const float* __restrict__ bias, void* __restrict__ outp, float oscale,
    int row0, int col0)
{
    __shared__ __half As[GSTAGES][128 * ALD];
    __shared__ __half Bs[GSTAGES][32 * BLD];

    const int tid = threadIdx.x;
    const int lane = tid & 31;
    const int g = lane >> 2;
    const int t = lane & 3;
    const int wid = tid >> 5;
    const int wm = (wid & 3) * 32;
    const int wn = (wid >> 2) * 64;

    float acc[2][8][4];
#pragma unroll
    for (int i = 0; i < 2; i++)
#pragma unroll
        for (int j = 0; j < 8; j++)
#pragma unroll
            for (int k = 0; k < 4; k++) acc[i][j][k] = 0.f;

    auto submit = [&](int k0, int st) {
#pragma unroll
        for (int i = 0; i < 2; i++) {
            int ci = tid + 256 * i;
            int ar = ci >> 2, ac = (ci & 3) * 8;
            cp16(smem_u32(&As[st][ar * ALD + ac]),
                 &X[(size_t)(row0 + ar) * 768 + k0 + ac]);
        }
#pragma unroll
        for (int i = 0; i < 2; i++) {
            int ci = tid + 256 * i;
            int br = ci >> 4, bc = (ci & 15) * 8;
            cp16(smem_u32(&Bs[st][br * BLD + bc]),
                 &W[(size_t)(k0 + br) * 768 + col0 + bc]);
        }
        cp_commit();
    };

    const int NK = 768 / 32;
    submit(0, 0);
    submit(32, 1);
    submit(64, 2);

    for (int k = 0; k < NK; k++) {
        const int s = k & (GSTAGES - 1);
        cp_wait2();
        __syncthreads();
        if (k + 3 < NK) submit((k + 3) * 32, (k + 3) & (GSTAGES - 1));

#pragma unroll
        for (int ks = 0; ks < 2; ks++) {
            unsigned a[2][4];
#pragma unroll
            for (int mt = 0; mt < 2; mt++)
                ldm4(a[mt][0], a[mt][1], a[mt][2], a[mt][3],
                     smem_u32(&As[s][(wm + mt * 16 + (lane & 15)) * ALD +
                                     ks * 16 + ((lane >> 4) << 3)]));
            unsigned b[4][4];
#pragma unroll
            for (int np = 0; np < 4; np++)
                ldm4t(b[np][0], b[np][1], b[np][2], b[np][3],
                      smem_u32(&Bs[s][(ks * 16 + (lane & 7) + ((lane >> 3) & 1) * 8) * BLD +
                                      wn + np * 16 + (lane >> 4) * 8]));
#pragma unroll
            for (int mt = 0; mt < 2; mt++)
#pragma unroll
                for (int np = 0; np < 4; np++) {
                    mma16816(acc[mt][np * 2], a[mt], b[np][0], b[np][1]);
                    mma16816(acc[mt][np * 2 + 1], a[mt], b[np][2], b[np][3]);
                }
        }
    }

#pragma unroll
    for (int nt = 0; nt < 8; nt++) {
        int col = col0 + wn + nt * 8 + 2 * t;
        float b0 = bias[col], b1 = bias[col + 1];
#pragma unroll
        for (int mt = 0; mt < 2; mt++)
#pragma unroll
            for (int hh = 0; hh < 2; hh++) {
                int m = row0 + wm + mt * 16 + g + hh * 8;
                float v0 = (acc[mt][nt][hh * 2] + b0) * oscale;
                float v1 = (acc[mt][nt][hh * 2 + 1] + b1) * oscale;
                if constexpr (OUT_HALF) {
                    __half* oh = (__half*)outp;
                    size_t idx;
                    if constexpr (SCATTER) {
                        int head = col >> 6, d = col & 63;
                        int bb = m >> 11, ss = m & 2047;
                        idx = ((size_t)(bb * NHEAD + head) * SEQ + ss) * HD + d;
                    } else {
                        idx = (size_t)m * 768 + col;
                    }
                    *(__half2*)&oh[idx] = __floats2half2_rn(v0, v1);
                } else {
                    float* of = (float*)outp;
                    float2 o; o.x = v0; o.y = v1;
                    *(float2*)&of[(size_t)m * 768 + col] = o;
                }
            }
    }
}

__global__ __launch_bounds__(256, 2) void gemm_qkv(
    const __half* __restrict__ X,
    const __half* __restrict__ Wq, const __half* __restrict__ Wk,
    const __half* __restrict__ Wv,
    const float* __restrict__ bq, const float* __restrict__ bk,
    const float* __restrict__ bv,
    __half* __restrict__ Qo, __half* __restrict__ Ko, __half* __restrict__ Vo,
    float qscale)
{
    const int z = blockIdx.z;
    const __half* W = (z == 0) ? Wq : (z == 1) ? Wk : Wv;
    const float* b  = (z == 0) ? bq : (z == 1) ? bk : bv;
    __half* o       = (z == 0) ? Qo : (z == 1) ? Ko : Vo;
    float sc        = (z == 0) ? qscale : 1.0f;
    gemm_body<true, true>(X, W, b, o, sc, blockIdx.y * 128, blockIdx.x * 128);
}

__global__ __launch_bounds__(256, 2) void gemm_out(
    const __half* __restrict__ X, const __half* __restrict__ W,
    const float* __restrict__ bias, float* __restrict__ out)
{
    gemm_body<false, false>(X, W, bias, out, 1.0f, blockIdx.y * 128, blockIdx.x * 128);
}

// ============================================================
// fp16 flash attention: q-tile 128, 4 warps x 32 q-rows,
// 64-key tiles, 3-stage cp.async, base-2 softmax w/ h2exp2.
// Fewer, fatter warps: per-CTA LDSM traffic halved vs 8x16.
// ============================================================
#define QLD 72
#define KVLD 72
#define ATHREADS 128

__global__ __launch_bounds__(ATHREADS, 2) void attn_f16(
    const __half* __restrict__ Qg, const __half* __restrict__ Kg,
    const __half* __restrict__ Vg, __half* __restrict__ ctx)
{
    extern __shared__ __half sm[];
    __half* Qs = sm;
    __half* KV = sm + 128 * QLD;

    const int tid = threadIdx.x;
    const int lane = tid & 31;
    const int g = lane >> 2;
    const int t = lane & 3;
    const int wid = tid >> 5;          // 0..3
    const int qr = wid * 32;           // 32 q-rows per warp
    const int bh = blockIdx.y;
    const int qt = blockIdx.x;

    const __half* Qp = Qg + ((size_t)bh * SEQ + qt * 128) * HD;
    const __half* Kbase = Kg + (size_t)bh * SEQ * HD;
    const __half* Vbase = Vg + (size_t)bh * SEQ * HD;

    const int NT = SEQ / 64;

    auto submit = [&](int kt, int st) {
        const __half* Kp = Kbase + (size_t)kt * 64 * HD;
        const __half* Vp = Vbase + (size_t)kt * 64 * HD;
        __half* Kd = KV + st * 2 * 64 * KVLD;
        __half* Vd = Kd + 64 * KVLD;
#pragma unroll
        for (int i = 0; i < 4; i++) {
            int ci = tid + ATHREADS * i;   // 512 chunks each of K and V
            int row = ci >> 3, c = ci & 7;
            cp16(smem_u32(&Kd[row * KVLD + c * 8]), &Kp[(size_t)row * HD + c * 8]);
            cp16(smem_u32(&Vd[row * KVLD + c * 8]), &Vp[(size_t)row * HD + c * 8]);
        }
        cp_commit();
    };

    submit(0, 0);
    submit(1, 1);
#pragma unroll
    for (int i = 0; i < 8; i++) {
        int ci = tid + ATHREADS * i;       // 1024 chunks of 8 halves
        int row = ci >> 3, c = ci & 7;
        *(uint4*)&Qs[row * QLD + c * 8] = *(const uint4*)&Qp[(size_t)row * HD + c * 8];
    }
    __syncthreads();

    // Q fragments: 2 x 16-row sets x 4 k-slices
    unsigned qa[2][4][4];
#pragma unroll
    for (int mt = 0; mt < 2; mt++)
#pragma unroll
        for (int ks = 0; ks < 4; ks++)
            ldm4(qa[mt][ks][0], qa[mt][ks][1], qa[mt][ks][2], qa[mt][ks][3],
                 smem_u32(&Qs[(qr + mt * 16 + (lane & 15)) * QLD +
                              ks * 16 + ((lane >> 4) << 3)]));

    float acc[2][8][4];
    float rowm[2][2], rowl[2][2];
#pragma unroll
    for (int mt = 0; mt < 2; mt++) {
#pragma unroll
        for (int hh = 0; hh < 2; hh++) { rowm[mt][hh] = -1e30f; rowl[mt][hh] = 0.f; }
#pragma unroll
        for (int i = 0; i < 8; i++)
#pragma unroll
            for (int j = 0; j < 4; j++) acc[mt][i][j] = 0.f;
    }

    for (int kt = 0; kt < NT; kt++) {
        const int s = kt % 3;
        cp_wait1();
        __syncthreads();
        if (kt + 2 < NT) submit(kt + 2, (kt + 2) % 3);

        const __half* Kd = KV + s * 2 * 64 * KVLD;
        const __half* Vd = Kd + 64 * KVLD;

        // ---- scores = Q @ K^T (32q x 64key per warp) ----
        float sc[2][8][4];
#pragma unroll
        for (int mt = 0; mt < 2; mt++)
#pragma unroll
            for (int i = 0; i < 8; i++)
#pragma unroll
                for (int j = 0; j < 4; j++) sc[mt][i][j] = 0.f;

#pragma unroll
        for (int ks = 0; ks < 4; ks++) {
            unsigned kb[4][4];
#pragma unroll
            for (int kp = 0; kp < 4; kp++)
                ldm4(kb[kp][0], kb[kp][1], kb[kp][2], kb[kp][3],
                     smem_u32(&Kd[(kp * 16 + (lane & 15)) * KVLD +
                                  ks * 16 + ((lane >> 4) << 3)]));
#pragma unroll
            for (int kp = 0; kp < 4; kp++)
#pragma unroll
                for (int mt = 0; mt < 2; mt++) {
                    mma16816(sc[mt][kp * 2],     qa[mt][ks], kb[kp][0], kb[kp][2]);
                    mma16816(sc[mt][kp * 2 + 1], qa[mt][ks], kb[kp][1], kb[kp][3]);
                }
        }

        // ---- online softmax, base-2 domain ----
        float newm[2][2], corr[2][2];
#pragma unroll
        for (int mt = 0; mt < 2; mt++)
#pragma unroll
            for (int hh = 0; hh < 2; hh++) {
                float mx = -1e30f;
#pragma unroll
                for (int nt = 0; nt < 8; nt++)
                    mx = fmaxf(mx, fmaxf(sc[mt][nt][hh * 2], sc[mt][nt][hh * 2 + 1]));
                mx = fmaxf(mx, __shfl_xor_sync(0xffffffffu, mx, 1));
                mx = fmaxf(mx, __shfl_xor_sync(0xffffffffu, mx, 2));
                newm[mt][hh] = fmaxf(rowm[mt][hh], mx);
                corr[mt][hh] = ex2f(rowm[mt][hh] - newm[mt][hh]);
                rowm[mt][hh] = newm[mt][hh];
#pragma unroll
                for (int nt = 0; nt < 8; nt++) {
                    acc[mt][nt][hh * 2] *= corr[mt][hh];
                    acc[mt][nt][hh * 2 + 1] *= corr[mt][hh];
                }
            }

        // ---- P = exp2(s - m), fp16x2 A-fragments ----
        unsigned ph[2][4][4];
#pragma unroll
        for (int mt = 0; mt < 2; mt++) {
            float ps0 = 0.f, ps1 = 0.f;
#pragma unroll
            for (int nt = 0; nt < 8; nt++) {
                __half2 e0 = h2exp2(__floats2half2_rn(sc[mt][nt][0] - newm[mt][0],
                                                      sc[mt][nt][1] - newm[mt][0]));
                __half2 e1 = h2exp2(__floats2half2_rn(sc[mt][nt][2] - newm[mt][1],
                                                      sc[mt][nt][3] - newm[mt][1]));
                ph[mt][nt >> 1][(nt & 1) * 2]     = *reinterpret_cast<unsigned*>(&e0);
                ph[mt][nt >> 1][(nt & 1) * 2 + 1] = *reinterpret_cast<unsigned*>(&e1);
                float2 f0 = __half22float2(e0);
                float2 f1 = __half22float2(e1);
                ps0 += f0.x + f0.y;
                ps1 += f1.x + f1.y;
            }
            ps0 += __shfl_xor_sync(0xffffffffu, ps0, 1);
            ps0 += __shfl_xor_sync(0xffffffffu, ps0, 2);
            ps1 += __shfl_xor_sync(0xffffffffu, ps1, 1);
            ps1 += __shfl_xor_sync(0xffffffffu, ps1, 2);
            rowl[mt][0] = rowl[mt][0] * corr[mt][0] + ps0;
            rowl[mt][1] = rowl[mt][1] * corr[mt][1] + ps1;
        }

        // ---- acc += P @ V (32q x 64d per warp) ----
#pragma unroll
        for (int ks = 0; ks < 4; ks++) {
            unsigned vb[4][4];
#pragma unroll
            for (int dp = 0; dp < 4; dp++)
                ldm4t(vb[dp][0], vb[dp][1], vb[dp][2], vb[dp][3],
                      smem_u32(&Vd[(ks * 16 + (lane & 7) + ((lane >> 3) & 1) * 8) * KVLD +
                                   dp * 16 + (lane >> 4) * 8]));
#pragma unroll
            for (int dp = 0; dp < 4; dp++)
#pragma unroll
                for (int mt = 0; mt < 2; mt++) {
                    mma16816(acc[mt][dp * 2],     ph[mt][ks], vb[dp][0], vb[dp][1]);
                    mma16816(acc[mt][dp * 2 + 1], ph[mt][ks], vb[dp][2], vb[dp][3]);
                }
        }
    }

    // ---- epilogue ----
    const int bb = bh / NHEAD;
    const int head = bh % NHEAD;
#pragma unroll
    for (int mt = 0; mt < 2; mt++)
#pragma unroll
        for (int hh = 0; hh < 2; hh++) {
            int q = qt * 128 + qr + mt * 16 + g + hh * 8;
            float inv = 1.f / rowl[mt][hh];
#pragma unroll
            for (int nt = 0; nt < 8; nt++) {
                int d = nt * 8 + 2 * t;
                *(__half2*)&ctx[(size_t)(bb * SEQ + q) * D_MODEL + head * HD + d] =
                    __floats2half2_rn(acc[mt][nt][hh * 2] * inv,
                                      acc[mt][nt][hh * 2 + 1] * inv);
            }
        }
}

// ============================================================
extern "C" void kernel_launch(void* const* d_in, const int* in_sizes, int n_in,
                              void* d_out, int out_size)
{
    const float* x  = (const float*)d_in[0];
    const float* Wq = (const float*)d_in[1];
    const float* bq = (const float*)d_in[2];
    const float* Wk = (const float*)d_in[3];
    const float* bk = (const float*)d_in[4];
    const float* Wv = (const float*)d_in[5];
    const float* bv = (const float*)d_in[6];
    const float* Wo = (const float*)d_in[7];
    const float* bo = (const float*)d_in[8];
    float* out = (float*)d_out;

    __half *Qp, *Kp, *Vp, *ctxp, *xh, *Wqh, *Wkh, *Wvh, *Woh;
    cudaGetSymbolAddress((void**)&Qp, g_Q);
    cudaGetSymbolAddress((void**)&Kp, g_K);
    cudaGetSymbolAddress((void**)&Vp, g_V);
    cudaGetSymbolAddress((void**)&ctxp, g_ctx);
    cudaGetSymbolAddress((void**)&xh, g_xh);
    cudaGetSymbolAddress((void**)&Wqh, g_Wqh);
    cudaGetSymbolAddress((void**)&Wkh, g_Wkh);
    cudaGetSymbolAddress((void**)&Wvh, g_Wvh);
    cudaGetSymbolAddress((void**)&Woh, g_Woh);

    const size_t attn_smem = (size_t)(128 * QLD + 6 * 64 * KVLD) * sizeof(__half);
    cudaFuncSetAttribute(attn_f16, cudaFuncAttributeMaxDynamicSharedMemorySize,
                         (int)attn_smem);

    cvt_all<<<(N8TOT + 255) / 256, 256>>>(x, Wq, Wk, Wv, Wo,
                                          xh, Wqh, Wkh, Wvh, Woh);

    const float QSCALE = 0.125f * 1.4426950408889634f;
    dim3 gq(768 / 128, MROWS / 128, 3);   // (6, 32, 3)
    gemm_qkv<<<gq, 256>>>(xh, Wqh, Wkh, Wvh, bq, bk, bv, Qp, Kp, Vp, QSCALE);

    dim3 ga(SEQ / 128, NBH);              // (16, 24)
    attn_f16<<<ga, ATHREADS, attn_smem>>>(Qp, Kp, Vp, ctxp);

    dim3 gg(768 / 128, MROWS / 128);      // (6, 32)
    gemm_out<<<gg, 256>>>(ctxp, Woh, bo, out);
}

// round 11
// speedup vs baseline: 1.1171x; 1.0117x over previous
#include <cuda_runtime.h>
#include <cuda_fp16.h>
#include <math.h>

#define D_MODEL 768
#define NHEAD 12
#define HD 64
#define BATCH 2
#define SEQ 2048
#define MROWS (BATCH*SEQ)   // 4096
#define NBH (BATCH*NHEAD)   // 24

// -------- scratch (fp16; no allocations) --------
__device__ __half g_Q[NBH*SEQ*HD];
__device__ __half g_K[NBH*SEQ*HD];
__device__ __half g_V[NBH*SEQ*HD];
__device__ __half g_ctx[MROWS*D_MODEL];
__device__ __half g_xh[MROWS*D_MODEL];
__device__ __half g_Wqh[D_MODEL*D_MODEL];
__device__ __half g_Wkh[D_MODEL*D_MODEL];
__device__ __half g_Wvh[D_MODEL*D_MODEL];
__device__ __half g_Woh[D_MODEL*D_MODEL];

// -------- helpers --------
__device__ __forceinline__ unsigned smem_u32(const void* p) {
    return (unsigned)__cvta_generic_to_shared(p);
}
__device__ __forceinline__ unsigned pack2(float a, float b) {
    __half2 h = __floats2half2_rn(a, b);
    return *reinterpret_cast<unsigned*>(&h);
}
__device__ __forceinline__ float ex2f(float x) {
    float r; asm("ex2.approx.f32 %0, %1;" : "=f"(r) : "f"(x)); return r;
}
__device__ __forceinline__ void ldm4(unsigned& r0, unsigned& r1, unsigned& r2, unsigned& r3,
                                     unsigned addr) {
    asm volatile("ldmatrix.sync.aligned.m8n8.x4.shared.b16 {%0,%1,%2,%3},[%4];"
                 : "=r"(r0), "=r"(r1), "=r"(r2), "=r"(r3) : "r"(addr));
}
__device__ __forceinline__ void ldm4t(unsigned& r0, unsigned& r1, unsigned& r2, unsigned& r3,
                                      unsigned addr) {
    asm volatile("ldmatrix.sync.aligned.m8n8.x4.trans.shared.b16 {%0,%1,%2,%3},[%4];"
                 : "=r"(r0), "=r"(r1), "=r"(r2), "=r"(r3) : "r"(addr));
}
__device__ __forceinline__ void mma16816(float* c, const unsigned* a, unsigned b0, unsigned b1) {
    asm volatile(
        "mma.sync.aligned.m16n8k16.row.col.f32.f16.f16.f32 "
        "{%0,%1,%2,%3},{%4,%5,%6,%7},{%8,%9},{%0,%1,%2,%3};"
        : "+f"(c[0]), "+f"(c[1]), "+f"(c[2]), "+f"(c[3])
        : "r"(a[0]), "r"(a[1]), "r"(a[2]), "r"(a[3]), "r"(b0), "r"(b1));
}
__device__ __forceinline__ void cp16(unsigned dst, const void* src) {
    asm volatile("cp.async.cg.shared.global [%0], [%1], 16;" :: "r"(dst), "l"(src));
}
__device__ __forceinline__ void cp_commit() { asm volatile("cp.async.commit_group;"); }
__device__ __forceinline__ void cp_wait1() { asm volatile("cp.async.wait_group 1;"); }
__device__ __forceinline__ void cp_wait0() { asm volatile("cp.async.wait_group 0;"); }

// ============================================================
// fused fp32 -> fp16 conversion of x + all 4 weights
// ============================================================
#define N8X (MROWS*D_MODEL/8)
#define N8W (D_MODEL*D_MODEL/8)
#define N8TOT (N8X + 4*N8W)

__global__ __launch_bounds__(256) void cvt_all(
    const float* __restrict__ x,
    const float* __restrict__ wq, const float* __restrict__ wk,
    const float* __restrict__ wv, const float* __restrict__ wo,
    __half* __restrict__ xh,
    __half* __restrict__ wqh, __half* __restrict__ wkh,
    __half* __restrict__ wvh, __half* __restrict__ woh)
{
    int i = blockIdx.x * 256 + threadIdx.x;
    if (i >= N8TOT) return;
    const float* src;
    __half* dst;
    int off;
    if (i < N8X) { src = x; dst = xh; off = i; }
    else {
        int j = i - N8X;
        int seg = j / N8W;
        off = j - seg * N8W;
        src = (seg == 0) ? wq : (seg == 1) ? wk : (seg == 2) ? wv : wo;
        dst = (seg == 0) ? wqh : (seg == 1) ? wkh : (seg == 2) ? wvh : woh;
    }
    float4 a = *(const float4*)&src[(size_t)off * 8];
    float4 b = *(const float4*)&src[(size_t)off * 8 + 4];
    uint4 h;
    h.x = pack2(a.x, a.y); h.y = pack2(a.z, a.w);
    h.z = pack2(b.x, b.y); h.w = pack2(b.z, b.w);
    *(uint4*)&dst[(size_t)off * 8] = h;
}

// ============================================================
// fp16 GEMM: 128m x 128n block, k-slab 64, 3-stage cp.async ring
// (prefetch depth 2), 256 thr = 8 warps (4m x 2n), warp 32m x 64n.
// 12 slabs -> 12 syncs (halved vs 32-wide slabs).
// ============================================================
#define ALD 72            // halves; 144B row stride, ldmatrix conflict-free
#define BLD 136
#define GSTAGE (128*ALD + 64*BLD)     // halves per stage: 9216+8704=17920
#define G_SMEM (3 * GSTAGE * 2)       // bytes: 107520

template<bool OUT_HALF, bool SCATTER>
__device__ __forceinline__ void gemm_body(
    const __half* __restrict__ X, const __half* __restrict__ W,
    const float* __restrict__ bias, void* __restrict__ outp, float oscale,
    int row0, int col0)
{
    extern __shared__ __half gsm[];

    const int tid = threadIdx.x;
    const int lane = tid & 31;
    const int g = lane >> 2;
    const int t = lane & 3;
    const int wid = tid >> 5;
    const int wm = (wid & 3) * 32;
    const int wn = (wid >> 2) * 64;

    float acc[2][8][4];
#pragma unroll
    for (int i = 0; i < 2; i++)
#pragma unroll
        for (int j = 0; j < 8; j++)
#pragma unroll
            for (int k = 0; k < 4; k++) acc[i][j][k] = 0.f;

    auto submit = [&](int slab, int st) {
        const int k0 = slab * 64;
        __half* As = gsm + st * GSTAGE;
        __half* Bs = As + 128 * ALD;
#pragma unroll
        for (int i = 0; i < 4; i++) {
            int ci = tid + 256 * i;              // 1024 chunks
            int ar = ci >> 3, ac = (ci & 7) * 8;
            cp16(smem_u32(&As[ar * ALD + ac]),
                 &X[(size_t)(row0 + ar) * 768 + k0 + ac]);
        }
#pragma unroll
        for (int i = 0; i < 4; i++) {
            int ci = tid + 256 * i;              // 1024 chunks
            int br = ci >> 4, bc = (ci & 15) * 8;
            cp16(smem_u32(&Bs[br * BLD + bc]),
                 &W[(size_t)(k0 + br) * 768 + col0 + bc]);
        }
        cp_commit();
    };

    const int NS = 768 / 64;    // 12
    submit(0, 0);
    submit(1, 1);

    for (int s = 0; s < NS; s++) {
        const int st = s % 3;
        cp_wait1();
        __syncthreads();
        if (s + 2 < NS) submit(s + 2, (s + 2) % 3);

        const __half* As = gsm + st * GSTAGE;
        const __half* Bs = As + 128 * ALD;

#pragma unroll
        for (int ks = 0; ks < 4; ks++) {
            unsigned a[2][4];
#pragma unroll
            for (int mt = 0; mt < 2; mt++)
                ldm4(a[mt][0], a[mt][1], a[mt][2], a[mt][3],
                     smem_u32(&As[(wm + mt * 16 + (lane & 15)) * ALD +
                                  ks * 16 + ((lane >> 4) << 3)]));
            unsigned b[4][4];
#pragma unroll
            for (int np = 0; np < 4; np++)
                ldm4t(b[np][0], b[np][1], b[np][2], b[np][3],
                      smem_u32(&Bs[(ks * 16 + (lane & 7) + ((lane >> 3) & 1) * 8) * BLD +
                                   wn + np * 16 + (lane >> 4) * 8]));
#pragma unroll
            for (int mt = 0; mt < 2; mt++)
#pragma unroll
                for (int np = 0; np < 4; np++) {
                    mma16816(acc[mt][np * 2], a[mt], b[np][0], b[np][1]);
                    mma16816(acc[mt][np * 2 + 1], a[mt], b[np][2], b[np][3]);
                }
        }
    }

#pragma unroll
    for (int nt = 0; nt < 8; nt++) {
        int col = col0 + wn + nt * 8 + 2 * t;
        float b0 = bias[col], b1 = bias[col + 1];
#pragma unroll
        for (int mt = 0; mt < 2; mt++)
#pragma unroll
            for (int hh = 0; hh < 2; hh++) {
                int m = row0 + wm + mt * 16 + g + hh * 8;
                float v0 = (acc[mt][nt][hh * 2] + b0) * oscale;
                float v1 = (acc[mt][nt][hh * 2 + 1] + b1) * oscale;
                if constexpr (OUT_HALF) {
                    __half* oh = (__half*)outp;
                    size_t idx;
                    if constexpr (SCATTER) {
                        int head = col >> 6, d = col & 63;
                        int bb = m >> 11, ss = m & 2047;
                        idx = ((size_t)(bb * NHEAD + head) * SEQ + ss) * HD + d;
                    } else {
                        idx = (size_t)m * 768 + col;
                    }
                    *(__half2*)&oh[idx] = __floats2half2_rn(v0, v1);
                } else {
                    float* of = (float*)outp;
                    float2 o; o.x = v0; o.y = v1;
                    *(float2*)&of[(size_t)m * 768 + col] = o;
                }
            }
    }
}

__global__ __launch_bounds__(256, 2) void gemm_qkv(
    const __half* __restrict__ X,
    const __half* __restrict__ Wq, const __half* __restrict__ Wk,
    const __half* __restrict__ Wv,
    const float* __restrict__ bq, const float* __restrict__ bk,
    const float* __restrict__ bv,
    __half* __restrict__ Qo, __half* __restrict__ Ko, __half* __restrict__ Vo,
    float qscale)
{
    const int z = blockIdx.z;
    const __half* W = (z == 0) ? Wq : (z == 1) ? Wk : Wv;
    const float* b  = (z == 0) ? bq : (z == 1) ? bk : bv;
    __half* o       = (z == 0) ? Qo : (z == 1) ? Ko : Vo;
    float sc        = (z == 0) ? qscale : 1.0f;
    gemm_body<true, true>(X, W, b, o, sc, blockIdx.y * 128, blockIdx.x * 128);
}

__global__ __launch_bounds__(256, 2) void gemm_out(
    const __half* __restrict__ X, const __half* __restrict__ W,
    const float* __restrict__ bias, float* __restrict__ out)
{
    gemm_body<false, false>(X, W, bias, out, 1.0f, blockIdx.y * 128, blockIdx.x * 128);
}

// ============================================================
// fp16 flash attention (R9, unchanged): q-tile 128, 4 warps x 32 q,
// 64-key tiles, 3-stage cp.async, base-2 softmax w/ h2exp2.
// ============================================================
#define QLD 72
#define KVLD 72
#define ATHREADS 128

__global__ __launch_bounds__(ATHREADS, 2) void attn_f16(
    const __half* __restrict__ Qg, const __half* __restrict__ Kg,
    const __half* __restrict__ Vg, __half* __restrict__ ctx)
{
    extern __shared__ __half sm[];
    __half* Qs = sm;
    __half* KV = sm + 128 * QLD;

    const int tid = threadIdx.x;
    const int lane = tid & 31;
    const int g = lane >> 2;
    const int t = lane & 3;
    const int wid = tid >> 5;
    const int qr = wid * 32;
    const int bh = blockIdx.y;
    const int qt = blockIdx.x;

    const __half* Qp = Qg + ((size_t)bh * SEQ + qt * 128) * HD;
    const __half* Kbase = Kg + (size_t)bh * SEQ * HD;
    const __half* Vbase = Vg + (size_t)bh * SEQ * HD;

    const int NT = SEQ / 64;

    auto submit = [&](int kt, int st) {
        const __half* Kp = Kbase + (size_t)kt * 64 * HD;
        const __half* Vp = Vbase + (size_t)kt * 64 * HD;
        __half* Kd = KV + st * 2 * 64 * KVLD;
        __half* Vd = Kd + 64 * KVLD;
#pragma unroll
        for (int i = 0; i < 4; i++) {
            int ci = tid + ATHREADS * i;
            int row = ci >> 3, c = ci & 7;
            cp16(smem_u32(&Kd[row * KVLD + c * 8]), &Kp[(size_t)row * HD + c * 8]);
            cp16(smem_u32(&Vd[row * KVLD + c * 8]), &Vp[(size_t)row * HD + c * 8]);
        }
        cp_commit();
    };

    submit(0, 0);
    submit(1, 1);
#pragma unroll
    for (int i = 0; i < 8; i++) {
        int ci = tid + ATHREADS * i;
        int row = ci >> 3, c = ci & 7;
        *(uint4*)&Qs[row * QLD + c * 8] = *(const uint4*)&Qp[(size_t)row * HD + c * 8];
    }
    __syncthreads();

    unsigned qa[2][4][4];
#pragma unroll
    for (int mt = 0; mt < 2; mt++)
#pragma unroll
        for (int ks = 0; ks < 4; ks++)
            ldm4(qa[mt][ks][0], qa[mt][ks][1], qa[mt][ks][2], qa[mt][ks][3],
                 smem_u32(&Qs[(qr + mt * 16 + (lane & 15)) * QLD +
                              ks * 16 + ((lane >> 4) << 3)]));

    float acc[2][8][4];
    float rowm[2][2], rowl[2][2];
#pragma unroll
    for (int mt = 0; mt < 2; mt++) {
#pragma unroll
        for (int hh = 0; hh < 2; hh++) { rowm[mt][hh] = -1e30f; rowl[mt][hh] = 0.f; }
#pragma unroll
        for (int i = 0; i < 8; i++)
#pragma unroll
            for (int j = 0; j < 4; j++) acc[mt][i][j] = 0.f;
    }

    for (int kt = 0; kt < NT; kt++) {
        const int s = kt % 3;
        cp_wait1();
        __syncthreads();
        if (kt + 2 < NT) submit(kt + 2, (kt + 2) % 3);

        const __half* Kd = KV + s * 2 * 64 * KVLD;
        const __half* Vd = Kd + 64 * KVLD;

        float sc[2][8][4];
#pragma unroll
        for (int mt = 0; mt < 2; mt++)
#pragma unroll
            for (int i = 0; i < 8; i++)
#pragma unroll
                for (int j = 0; j < 4; j++) sc[mt][i][j] = 0.f;

#pragma unroll
        for (int ks = 0; ks < 4; ks++) {
            unsigned kb[4][4];
#pragma unroll
            for (int kp = 0; kp < 4; kp++)
                ldm4(kb[kp][0], kb[kp][1], kb[kp][2], kb[kp][3],
                     smem_u32(&Kd[(kp * 16 + (lane & 15)) * KVLD +
                                  ks * 16 + ((lane >> 4) << 3)]));
#pragma unroll
            for (int kp = 0; kp < 4; kp++)
#pragma unroll
                for (int mt = 0; mt < 2; mt++) {
                    mma16816(sc[mt][kp * 2],     qa[mt][ks], kb[kp][0], kb[kp][2]);
                    mma16816(sc[mt][kp * 2 + 1], qa[mt][ks], kb[kp][1], kb[kp][3]);
                }
        }

        float newm[2][2], corr[2][2];
#pragma unroll
        for (int mt = 0; mt < 2; mt++)
#pragma unroll
            for (int hh = 0; hh < 2; hh++) {
                float mx = -1e30f;
#pragma unroll
                for (int nt = 0; nt < 8; nt++)
                    mx = fmaxf(mx, fmaxf(sc[mt][nt][hh * 2], sc[mt][nt][hh * 2 + 1]));
                mx = fmaxf(mx, __shfl_xor_sync(0xffffffffu, mx, 1));
                mx = fmaxf(mx, __shfl_xor_sync(0xffffffffu, mx, 2));
                newm[mt][hh] = fmaxf(rowm[mt][hh], mx);
                corr[mt][hh] = ex2f(rowm[mt][hh] - newm[mt][hh]);
                rowm[mt][hh] = newm[mt][hh];
#pragma unroll
                for (int nt = 0; nt < 8; nt++) {
                    acc[mt][nt][hh * 2] *= corr[mt][hh];
                    acc[mt][nt][hh * 2 + 1] *= corr[mt][hh];
                }
            }

        unsigned ph[2][4][4];
#pragma unroll
        for (int mt = 0; mt < 2; mt++) {
            float ps0 = 0.f, ps1 = 0.f;
#pragma unroll
            for (int nt = 0; nt < 8; nt++) {
                __half2 e0 = h2exp2(__floats2half2_rn(sc[mt][nt][0] - newm[mt][0],
                                                      sc[mt][nt][1] - newm[mt][0]));
                __half2 e1 = h2exp2(__floats2half2_rn(sc[mt][nt][2] - newm[mt][1],
                                                      sc[mt][nt][3] - newm[mt][1]));
                ph[mt][nt >> 1][(nt & 1) * 2]     = *reinterpret_cast<unsigned*>(&e0);
                ph[mt][nt >> 1][(nt & 1) * 2 + 1] = *reinterpret_cast<unsigned*>(&e1);
                float2 f0 = __half22float2(e0);
                float2 f1 = __half22float2(e1);
                ps0 += f0.x + f0.y;
                ps1 += f1.x + f1.y;
            }
            ps0 += __shfl_xor_sync(0xffffffffu, ps0, 1);
            ps0 += __shfl_xor_sync(0xffffffffu, ps0, 2);
            ps1 += __shfl_xor_sync(0xffffffffu, ps1, 1);
            ps1 += __shfl_xor_sync(0xffffffffu, ps1, 2);
            rowl[mt][0] = rowl[mt][0] * corr[mt][0] + ps0;
            rowl[mt][1] = rowl[mt][1] * corr[mt][1] + ps1;
        }

#pragma unroll
        for (int ks = 0; ks < 4; ks++) {
            unsigned vb[4][4];
#pragma unroll
            for (int dp = 0; dp < 4; dp++)
                ldm4t(vb[dp][0], vb[dp][1], vb[dp][2], vb[dp][3],
                      smem_u32(&Vd[(ks * 16 + (lane & 7) + ((lane >> 3) & 1) * 8) * KVLD +
                                   dp * 16 + (lane >> 4) * 8]));
#pragma unroll
            for (int dp = 0; dp < 4; dp++)
#pragma unroll
                for (int mt = 0; mt < 2; mt++) {
                    mma16816(acc[mt][dp * 2],     ph[mt][ks], vb[dp][0], vb[dp][1]);
                    mma16816(acc[mt][dp * 2 + 1], ph[mt][ks], vb[dp][2], vb[dp][3]);
                }
        }
    }

    const int bb = bh / NHEAD;
    const int head = bh % NHEAD;
#pragma unroll
    for (int mt = 0; mt < 2; mt++)
#pragma unroll
        for (int hh = 0; hh < 2; hh++) {
            int q = qt * 128 + qr + mt * 16 + g + hh * 8;
            float inv = 1.f / rowl[mt][hh];
#pragma unroll
            for (int nt = 0; nt < 8; nt++) {
                int d = nt * 8 + 2 * t;
                *(__half2*)&ctx[(size_t)(bb * SEQ + q) * D_MODEL + head * HD + d] =
                    __floats2half2_rn(acc[mt][nt][hh * 2] * inv,
                                      acc[mt][nt][hh * 2 + 1] * inv);
            }
        }
}

// ============================================================
extern "C" void kernel_launch(void* const* d_in, const int* in_sizes, int n_in,
                              void* d_out, int out_size)
{
    const float* x  = (const float*)d_in[0];
    const float* Wq = (const float*)d_in[1];
    const float* bq = (const float*)d_in[2];
    const float* Wk = (const float*)d_in[3];
    const float* bk = (const float*)d_in[4];
    const float* Wv = (const float*)d_in[5];
    const float* bv = (const float*)d_in[6];
    const float* Wo = (const float*)d_in[7];
    const float* bo = (const float*)d_in[8];
    float* out = (float*)d_out;

    __half *Qp, *Kp, *Vp, *ctxp, *xh, *Wqh, *Wkh, *Wvh, *Woh;
    cudaGetSymbolAddress((void**)&Qp, g_Q);
    cudaGetSymbolAddress((void**)&Kp, g_K);
    cudaGetSymbolAddress((void**)&Vp, g_V);
    cudaGetSymbolAddress((void**)&ctxp, g_ctx);
    cudaGetSymbolAddress((void**)&xh, g_xh);
    cudaGetSymbolAddress((void**)&Wqh, g_Wqh);
    cudaGetSymbolAddress((void**)&Wkh, g_Wkh);
    cudaGetSymbolAddress((void**)&Wvh, g_Wvh);
    cudaGetSymbolAddress((void**)&Woh, g_Woh);

    const size_t attn_smem = (size_t)(128 * QLD + 6 * 64 * KVLD) * sizeof(__half);
    cudaFuncSetAttribute(attn_f16, cudaFuncAttributeMaxDynamicSharedMemorySize,
                         (int)attn_smem);
    cudaFuncSetAttribute(gemm_qkv, cudaFuncAttributeMaxDynamicSharedMemorySize, G_SMEM);
    cudaFuncSetAttribute(gemm_out, cudaFuncAttributeMaxDynamicSharedMemorySize, G_SMEM);

    cvt_all<<<(N8TOT + 255) / 256, 256>>>(x, Wq, Wk, Wv, Wo,
                                          xh, Wqh, Wkh, Wvh, Woh);

    const float QSCALE = 0.125f * 1.4426950408889634f;
    dim3 gq(768 / 128, MROWS / 128, 3);   // (6, 32, 3)
    gemm_qkv<<<gq, 256, G_SMEM>>>(xh, Wqh, Wkh, Wvh, bq, bk, bv, Qp, Kp, Vp, QSCALE);

    dim3 ga(SEQ / 128, NBH);              // (16, 24)
    attn_f16<<<ga, ATHREADS, attn_smem>>>(Qp, Kp, Vp, ctxp);

    dim3 gg(768 / 128, MROWS / 128);      // (6, 32)
    gemm_out<<<gg, 256, G_SMEM>>>(ctxp, Woh, bo, out);
}

// round 12
// speedup vs baseline: 1.1283x; 1.0100x over previous
#include <cuda_runtime.h>
#include <cuda_fp16.h>
#include <math.h>

#define D_MODEL 768
#define NHEAD 12
#define HD 64
#define BATCH 2
#define SEQ 2048
#define MROWS (BATCH*SEQ)   // 4096
#define NBH (BATCH*NHEAD)   // 24

// -------- scratch (fp16; no allocations) --------
__device__ __half g_Q[NBH*SEQ*HD];
__device__ __half g_K[NBH*SEQ*HD];
__device__ __half g_V[NBH*SEQ*HD];
__device__ __half g_ctx[MROWS*D_MODEL];
__device__ __half g_xh[MROWS*D_MODEL];
__device__ __half g_Wqh[D_MODEL*D_MODEL];
__device__ __half g_Wkh[D_MODEL*D_MODEL];
__device__ __half g_Wvh[D_MODEL*D_MODEL];
__device__ __half g_Woh[D_MODEL*D_MODEL];

// -------- helpers --------
__device__ __forceinline__ unsigned smem_u32(const void* p) {
    return (unsigned)__cvta_generic_to_shared(p);
}
__device__ __forceinline__ unsigned pack2(float a, float b) {
    __half2 h = __floats2half2_rn(a, b);
    return *reinterpret_cast<unsigned*>(&h);
}
__device__ __forceinline__ float ex2f(float x) {
    float r; asm("ex2.approx.f32 %0, %1;" : "=f"(r) : "f"(x)); return r;
}
__device__ __forceinline__ void ldm4(unsigned& r0, unsigned& r1, unsigned& r2, unsigned& r3,
                                     unsigned addr) {
    asm volatile("ldmatrix.sync.aligned.m8n8.x4.shared.b16 {%0,%1,%2,%3},[%4];"
                 : "=r"(r0), "=r"(r1), "=r"(r2), "=r"(r3) : "r"(addr));
}
__device__ __forceinline__ void ldm4t(unsigned& r0, unsigned& r1, unsigned& r2, unsigned& r3,
                                      unsigned addr) {
    asm volatile("ldmatrix.sync.aligned.m8n8.x4.trans.shared.b16 {%0,%1,%2,%3},[%4];"
                 : "=r"(r0), "=r"(r1), "=r"(r2), "=r"(r3) : "r"(addr));
}
__device__ __forceinline__ void mma16816(float* c, const unsigned* a, unsigned b0, unsigned b1) {
    asm volatile(
        "mma.sync.aligned.m16n8k16.row.col.f32.f16.f16.f32 "
        "{%0,%1,%2,%3},{%4,%5,%6,%7},{%8,%9},{%0,%1,%2,%3};"
        : "+f"(c[0]), "+f"(c[1]), "+f"(c[2]), "+f"(c[3])
        : "r"(a[0]), "r"(a[1]), "r"(a[2]), "r"(a[3]), "r"(b0), "r"(b1));
}
__device__ __forceinline__ void cp16(unsigned dst, const void* src) {
    asm volatile("cp.async.cg.shared.global [%0], [%1], 16;" :: "r"(dst), "l"(src));
}
__device__ __forceinline__ void cp_commit() { asm volatile("cp.async.commit_group;"); }
__device__ __forceinline__ void cp_wait2() { asm volatile("cp.async.wait_group 2;"); }
__device__ __forceinline__ void cp_wait1() { asm volatile("cp.async.wait_group 1;"); }
__device__ __forceinline__ void cp_wait0() { asm volatile("cp.async.wait_group 0;"); }

// ============================================================
// fused fp32 -> fp16 conversion of x + all 4 weights
// ============================================================
#define N8X (MROWS*D_MODEL/8)
#define N8W (D_MODEL*D_MODEL/8)
#define N8TOT (N8X + 4*N8W)

__global__ __launch_bounds__(256) void cvt_all(
    const float* __restrict__ x,
    const float* __restrict__ wq, const float* __restrict__ wk,
    const float* __restrict__ wv, const float* __restrict__ wo,
    __half* __restrict__ xh,
    __half* __restrict__ wqh, __half* __restrict__ wkh,
    __half* __restrict__ wvh, __half* __restrict__ woh)
{
    int i = blockIdx.x * 256 + threadIdx.x;
    if (i >= N8TOT) return;
    const float* src;
    __half* dst;
    int off;
    if (i < N8X) { src = x; dst = xh; off = i; }
    else {
        int j = i - N8X;
        int seg = j / N8W;
        off = j - seg * N8W;
        src = (seg == 0) ? wq : (seg == 1) ? wk : (seg == 2) ? wv : wo;
        dst = (seg == 0) ? wqh : (seg == 1) ? wkh : (seg == 2) ? wvh : woh;
    }
    float4 a = *(const float4*)&src[(size_t)off * 8];
    float4 b = *(const float4*)&src[(size_t)off * 8 + 4];
    uint4 h;
    h.x = pack2(a.x, a.y); h.y = pack2(a.z, a.w);
    h.z = pack2(b.x, b.y); h.w = pack2(b.z, b.w);
    *(uint4*)&dst[(size_t)off * 8] = h;
}

// ============================================================
// fp16 GEMM (R11 config): 128m x 128n block, k-slab 64,
// 3-stage cp.async ring, 256 thr = 8 warps (4m x 2n).
// ============================================================
#define ALD 72
#define BLD 136
#define GSTAGE (128*ALD + 64*BLD)     // halves per stage
#define G_SMEM (3 * GSTAGE * 2)       // bytes

template<bool OUT_HALF, bool SCATTER>
__device__ __forceinline__ void gemm_body(
    const __half* __restrict__ X, const __half* __restrict__ W,
    const float* __restrict__ bias, void* __restrict__ outp, float oscale,
    int row0, int col0)
{
    extern __shared__ __half gsm[];

    const int tid = threadIdx.x;
    const int lane = tid & 31;
    const int g = lane >> 2;
    const int t = lane & 3;
    const int wid = tid >> 5;
    const int wm = (wid & 3) * 32;
    const int wn = (wid >> 2) * 64;

    float acc[2][8][4];
#pragma unroll
    for (int i = 0; i < 2; i++)
#pragma unroll
        for (int j = 0; j < 8; j++)
#pragma unroll
            for (int k = 0; k < 4; k++) acc[i][j][k] = 0.f;

    auto submit = [&](int slab, int st) {
        const int k0 = slab * 64;
        __half* As = gsm + st * GSTAGE;
        __half* Bs = As + 128 * ALD;
#pragma unroll
        for (int i = 0; i < 4; i++) {
            int ci = tid + 256 * i;
            int ar = ci >> 3, ac = (ci & 7) * 8;
            cp16(smem_u32(&As[ar * ALD + ac]),
                 &X[(size_t)(row0 + ar) * 768 + k0 + ac]);
        }
#pragma unroll
        for (int i = 0; i < 4; i++) {
            int ci = tid + 256 * i;
            int br = ci >> 4, bc = (ci & 15) * 8;
            cp16(smem_u32(&Bs[br * BLD + bc]),
                 &W[(size_t)(k0 + br) * 768 + col0 + bc]);
        }
        cp_commit();
    };

    const int NS = 768 / 64;    // 12
    submit(0, 0);
    submit(1, 1);

    for (int s = 0; s < NS; s++) {
        const int st = s % 3;
        cp_wait1();
        __syncthreads();
        if (s + 2 < NS) submit(s + 2, (s + 2) % 3);

        const __half* As = gsm + st * GSTAGE;
        const __half* Bs = As + 128 * ALD;

#pragma unroll
        for (int ks = 0; ks < 4; ks++) {
            unsigned a[2][4];
#pragma unroll
            for (int mt = 0; mt < 2; mt++)
                ldm4(a[mt][0], a[mt][1], a[mt][2], a[mt][3],
                     smem_u32(&As[(wm + mt * 16 + (lane & 15)) * ALD +
                                  ks * 16 + ((lane >> 4) << 3)]));
            unsigned b[4][4];
#pragma unroll
            for (int np = 0; np < 4; np++)
                ldm4t(b[np][0], b[np][1], b[np][2], b[np][3],
                      smem_u32(&Bs[(ks * 16 + (lane & 7) + ((lane >> 3) & 1) * 8) * BLD +
                                   wn + np * 16 + (lane >> 4) * 8]));
#pragma unroll
            for (int mt = 0; mt < 2; mt++)
#pragma unroll
                for (int np = 0; np < 4; np++) {
                    mma16816(acc[mt][np * 2], a[mt], b[np][0], b[np][1]);
                    mma16816(acc[mt][np * 2 + 1], a[mt], b[np][2], b[np][3]);
                }
        }
    }

#pragma unroll
    for (int nt = 0; nt < 8; nt++) {
        int col = col0 + wn + nt * 8 + 2 * t;
        float b0 = bias[col], b1 = bias[col + 1];
#pragma unroll
        for (int mt = 0; mt < 2; mt++)
#pragma unroll
            for (int hh = 0; hh < 2; hh++) {
                int m = row0 + wm + mt * 16 + g + hh * 8;
                float v0 = (acc[mt][nt][hh * 2] + b0) * oscale;
                float v1 = (acc[mt][nt][hh * 2 + 1] + b1) * oscale;
                if constexpr (OUT_HALF) {
                    __half* oh = (__half*)outp;
                    size_t idx;
                    if constexpr (SCATTER) {
                        int head = col >> 6, d = col & 63;
                        int bb = m >> 11, ss = m & 2047;
                        idx = ((size_t)(bb * NHEAD + head) * SEQ + ss) * HD + d;
                    } else {
                        idx = (size_t)m * 768 + col;
                    }
                    *(__half2*)&oh[idx] = __floats2half2_rn(v0, v1);
                } else {
                    float* of = (float*)outp;
                    float2 o; o.x = v0; o.y = v1;
                    *(float2*)&of[(size_t)m * 768 + col] = o;
                }
            }
    }
}

__global__ __launch_bounds__(256, 2) void gemm_qkv(
    const __half* __restrict__ X,
    const __half* __restrict__ Wq, const __half* __restrict__ Wk,
    const __half* __restrict__ Wv,
    const float* __restrict__ bq, const float* __restrict__ bk,
    const float* __restrict__ bv,
    __half* __restrict__ Qo, __half* __restrict__ Ko, __half* __restrict__ Vo,
    float qscale)
{
    const int z = blockIdx.z;
    const __half* W = (z == 0) ? Wq : (z == 1) ? Wk : Wv;
    const float* b  = (z == 0) ? bq : (z == 1) ? bk : bv;
    __half* o       = (z == 0) ? Qo : (z == 1) ? Ko : Vo;
    float sc        = (z == 0) ? qscale : 1.0f;
    gemm_body<true, true>(X, W, b, o, sc, blockIdx.y * 128, blockIdx.x * 128);
}

__global__ __launch_bounds__(256, 2) void gemm_out(
    const __half* __restrict__ X, const __half* __restrict__ W,
    const float* __restrict__ bias, float* __restrict__ out)
{
    gemm_body<false, false>(X, W, bias, out, 1.0f, blockIdx.y * 128, blockIdx.x * 128);
}

// ============================================================
// fp16 flash attention: q-tile 128, 4 warps x 32 q-rows,
// 64-key tiles, 4-stage cp.async ring (prefetch depth 3).
// ============================================================
#define QLD 72
#define KVLD 72
#define ATHREADS 128
#define KVSTAGES 4

__global__ __launch_bounds__(ATHREADS, 2) void attn_f16(
    const __half* __restrict__ Qg, const __half* __restrict__ Kg,
    const __half* __restrict__ Vg, __half* __restrict__ ctx)
{
    extern __shared__ __half sm[];
    __half* Qs = sm;
    __half* KV = sm + 128 * QLD;

    const int tid = threadIdx.x;
    const int lane = tid & 31;
    const int g = lane >> 2;
    const int t = lane & 3;
    const int wid = tid >> 5;
    const int qr = wid * 32;
    const int bh = blockIdx.y;
    const int qt = blockIdx.x;

    const __half* Qp = Qg + ((size_t)bh * SEQ + qt * 128) * HD;
    const __half* Kbase = Kg + (size_t)bh * SEQ * HD;
    const __half* Vbase = Vg + (size_t)bh * SEQ * HD;

    const int NT = SEQ / 64;

    auto submit = [&](int kt, int st) {
        const __half* Kp = Kbase + (size_t)kt * 64 * HD;
        const __half* Vp = Vbase + (size_t)kt * 64 * HD;
        __half* Kd = KV + st * 2 * 64 * KVLD;
        __half* Vd = Kd + 64 * KVLD;
#pragma unroll
        for (int i = 0; i < 4; i++) {
            int ci = tid + ATHREADS * i;
            int row = ci >> 3, c = ci & 7;
            cp16(smem_u32(&Kd[row * KVLD + c * 8]), &Kp[(size_t)row * HD + c * 8]);
            cp16(smem_u32(&Vd[row * KVLD + c * 8]), &Vp[(size_t)row * HD + c * 8]);
        }
        cp_commit();
    };

    submit(0, 0);
    submit(1, 1);
    submit(2, 2);
#pragma unroll
    for (int i = 0; i < 8; i++) {
        int ci = tid + ATHREADS * i;
        int row = ci >> 3, c = ci & 7;
        *(uint4*)&Qs[row * QLD + c * 8] = *(const uint4*)&Qp[(size_t)row * HD + c * 8];
    }
    __syncthreads();

    unsigned qa[2][4][4];
#pragma unroll
    for (int mt = 0; mt < 2; mt++)
#pragma unroll
        for (int ks = 0; ks < 4; ks++)
            ldm4(qa[mt][ks][0], qa[mt][ks][1], qa[mt][ks][2], qa[mt][ks][3],
                 smem_u32(&Qs[(qr + mt * 16 + (lane & 15)) * QLD +
                              ks * 16 + ((lane >> 4) << 3)]));

    float acc[2][8][4];
    float rowm[2][2], rowl[2][2];
#pragma unroll
    for (int mt = 0; mt < 2; mt++) {
#pragma unroll
        for (int hh = 0; hh < 2; hh++) { rowm[mt][hh] = -1e30f; rowl[mt][hh] = 0.f; }
#pragma unroll
        for (int i = 0; i < 8; i++)
#pragma unroll
            for (int j = 0; j < 4; j++) acc[mt][i][j] = 0.f;
    }

    for (int kt = 0; kt < NT; kt++) {
        const int s = kt % KVSTAGES;
        cp_wait2();
        __syncthreads();
        if (kt + 3 < NT) submit(kt + 3, (kt + 3) % KVSTAGES);

        const __half* Kd = KV + s * 2 * 64 * KVLD;
        const __half* Vd = Kd + 64 * KVLD;

        float sc[2][8][4];
#pragma unroll
        for (int mt = 0; mt < 2; mt++)
#pragma unroll
            for (int i = 0; i < 8; i++)
#pragma unroll
                for (int j = 0; j < 4; j++) sc[mt][i][j] = 0.f;

#pragma unroll
        for (int ks = 0; ks < 4; ks++) {
            unsigned kb[4][4];
#pragma unroll
            for (int kp = 0; kp < 4; kp++)
                ldm4(kb[kp][0], kb[kp][1], kb[kp][2], kb[kp][3],
                     smem_u32(&Kd[(kp * 16 + (lane & 15)) * KVLD +
                                  ks * 16 + ((lane >> 4) << 3)]));
#pragma unroll
            for (int kp = 0; kp < 4; kp++)
#pragma unroll
                for (int mt = 0; mt < 2; mt++) {
                    mma16816(sc[mt][kp * 2],     qa[mt][ks], kb[kp][0], kb[kp][2]);
                    mma16816(sc[mt][kp * 2 + 1], qa[mt][ks], kb[kp][1], kb[kp][3]);
                }
        }

        float newm[2][2], corr[2][2];
#pragma unroll
        for (int mt = 0; mt < 2; mt++)
#pragma unroll
            for (int hh = 0; hh < 2; hh++) {
                float mx = -1e30f;
#pragma unroll
                for (int nt = 0; nt < 8; nt++)
                    mx = fmaxf(mx, fmaxf(sc[mt][nt][hh * 2], sc[mt][nt][hh * 2 + 1]));
                mx = fmaxf(mx, __shfl_xor_sync(0xffffffffu, mx, 1));
                mx = fmaxf(mx, __shfl_xor_sync(0xffffffffu, mx, 2));
                newm[mt][hh] = fmaxf(rowm[mt][hh], mx);
                corr[mt][hh] = ex2f(rowm[mt][hh] - newm[mt][hh]);
                rowm[mt][hh] = newm[mt][hh];
#pragma unroll
                for (int nt = 0; nt < 8; nt++) {
                    acc[mt][nt][hh * 2] *= corr[mt][hh];
                    acc[mt][nt][hh * 2 + 1] *= corr[mt][hh];
                }
            }

        unsigned ph[2][4][4];
#pragma unroll
        for (int mt = 0; mt < 2; mt++) {
            float ps0 = 0.f, ps1 = 0.f;
#pragma unroll
            for (int nt = 0; nt < 8; nt++) {
                __half2 e0 = h2exp2(__floats2half2_rn(sc[mt][nt][0] - newm[mt][0],
                                                      sc[mt][nt][1] - newm[mt][0]));
                __half2 e1 = h2exp2(__floats2half2_rn(sc[mt][nt][2] - newm[mt][1],
                                                      sc[mt][nt][3] - newm[mt][1]));
                ph[mt][nt >> 1][(nt & 1) * 2]     = *reinterpret_cast<unsigned*>(&e0);
                ph[mt][nt >> 1][(nt & 1) * 2 + 1] = *reinterpret_cast<unsigned*>(&e1);
                float2 f0 = __half22float2(e0);
                float2 f1 = __half22float2(e1);
                ps0 += f0.x + f0.y;
                ps1 += f1.x + f1.y;
            }
            ps0 += __shfl_xor_sync(0xffffffffu, ps0, 1);
            ps0 += __shfl_xor_sync(0xffffffffu, ps0, 2);
            ps1 += __shfl_xor_sync(0xffffffffu, ps1, 1);
            ps1 += __shfl_xor_sync(0xffffffffu, ps1, 2);
            rowl[mt][0] = rowl[mt][0] * corr[mt][0] + ps0;
            rowl[mt][1] = rowl[mt][1] * corr[mt][1] + ps1;
        }

#pragma unroll
        for (int ks = 0; ks < 4; ks++) {
            unsigned vb[4][4];
#pragma unroll
            for (int dp = 0; dp < 4; dp++)
                ldm4t(vb[dp][0], vb[dp][1], vb[dp][2], vb[dp][3],
                      smem_u32(&Vd[(ks * 16 + (lane & 7) + ((lane >> 3) & 1) * 8) * KVLD +
                                   dp * 16 + (lane >> 4) * 8]));
#pragma unroll
            for (int dp = 0; dp < 4; dp++)
#pragma unroll
                for (int mt = 0; mt < 2; mt++) {
                    mma16816(acc[mt][dp * 2],     ph[mt][ks], vb[dp][0], vb[dp][1]);
                    mma16816(acc[mt][dp * 2 + 1], ph[mt][ks], vb[dp][2], vb[dp][3]);
                }
        }
    }

    const int bb = bh / NHEAD;
    const int head = bh % NHEAD;
#pragma unroll
    for (int mt = 0; mt < 2; mt++)
#pragma unroll
        for (int hh = 0; hh < 2; hh++) {
            int q = qt * 128 + qr + mt * 16 + g + hh * 8;
            float inv = 1.f / rowl[mt][hh];
#pragma unroll
            for (int nt = 0; nt < 8; nt++) {
                int d = nt * 8 + 2 * t;
                *(__half2*)&ctx[(size_t)(bb * SEQ + q) * D_MODEL + head * HD + d] =
                    __floats2half2_rn(acc[mt][nt][hh * 2] * inv,
                                      acc[mt][nt][hh * 2 + 1] * inv);
            }
        }
}

// ============================================================
extern "C" void kernel_launch(void* const* d_in, const int* in_sizes, int n_in,
                              void* d_out, int out_size)
{
    const float* x  = (const float*)d_in[0];
    const float* Wq = (const float*)d_in[1];
    const float* bq = (const float*)d_in[2];
    const float* Wk = (const float*)d_in[3];
    const float* bk = (const float*)d_in[4];
    const float* Wv = (const float*)d_in[5];
    const float* bv = (const float*)d_in[6];
    const float* Wo = (const float*)d_in[7];
    const float* bo = (const float*)d_in[8];
    float* out = (float*)d_out;

    __half *Qp, *Kp, *Vp, *ctxp, *xh, *Wqh, *Wkh, *Wvh, *Woh;
    cudaGetSymbolAddress((void**)&Qp, g_Q);
    cudaGetSymbolAddress((void**)&Kp, g_K);
    cudaGetSymbolAddress((void**)&Vp, g_V);
    cudaGetSymbolAddress((void**)&ctxp, g_ctx);
    cudaGetSymbolAddress((void**)&xh, g_xh);
    cudaGetSymbolAddress((void**)&Wqh, g_Wqh);
    cudaGetSymbolAddress((void**)&Wkh, g_Wkh);
    cudaGetSymbolAddress((void**)&Wvh, g_Wvh);
    cudaGetSymbolAddress((void**)&Woh, g_Woh);

    const size_t attn_smem =
        (size_t)(128 * QLD + 2 * KVSTAGES * 64 * KVLD) * sizeof(__half);
    cudaFuncSetAttribute(attn_f16, cudaFuncAttributeMaxDynamicSharedMemorySize,
                         (int)attn_smem);
    cudaFuncSetAttribute(gemm_qkv, cudaFuncAttributeMaxDynamicSharedMemorySize, G_SMEM);
    cudaFuncSetAttribute(gemm_out, cudaFuncAttributeMaxDynamicSharedMemorySize, G_SMEM);

    cvt_all<<<(N8TOT + 255) / 256, 256>>>(x, Wq, Wk, Wv, Wo,
                                          xh, Wqh, Wkh, Wvh, Woh);

    const float QSCALE = 0.125f * 1.4426950408889634f;
    dim3 gq(768 / 128, MROWS / 128, 3);   // (6, 32, 3)
    gemm_qkv<<<gq, 256, G_SMEM>>>(xh, Wqh, Wkh, Wvh, bq, bk, bv, Qp, Kp, Vp, QSCALE);

    dim3 ga(SEQ / 128, NBH);              // (16, 24)
    attn_f16<<<ga, ATHREADS, attn_smem>>>(Qp, Kp, Vp, ctxp);

    dim3 gg(768 / 128, MROWS / 128);      // (6, 32)
    gemm_out<<<gg, 256, G_SMEM>>>(ctxp, Woh, bo, out);
}